// round 1
// baseline (speedup 1.0000x reference)
#include <cuda_runtime.h>
#include <math.h>

// ---------------- problem constants ----------------
constexpr int Bb  = 256;
constexpr int Tt  = 64;
constexpr int Aa  = 64;
constexpr int Ee  = 1024;
constexpr int HIDn = 1024;
constexpr int DETn = 2048;
constexpr int STOn = 256;
constexpr int G3  = 3 * DETn;   // 6144

// ---------------- scratch (device globals; no allocation allowed) ----------------
__device__ float g_z  [Bb * STOn];
__device__ float g_h  [Bb * DETn];
__device__ float g_rnn[Bb * HIDn];
__device__ float g_gi [Bb * G3];
__device__ float g_gh [Bb * G3];
__device__ float g_pf [Bb * HIDn];
__device__ float g_rf [Bb * HIDn];

// ---------------- packed f32x2 FMA (full-rate fp32 path on sm_103a) ----------------
__device__ __forceinline__ unsigned long long ffma2(unsigned long long a,
                                                    unsigned long long b,
                                                    unsigned long long c) {
    unsigned long long d;
    asm("fma.rn.f32x2 %0, %1, %2, %3;" : "=l"(d) : "l"(a), "l"(b), "l"(c));
    return d;
}

// ---------------- generic fused GEMM ----------------
// C[M,N] = act( [A1 | A2] @ W + bias ),  M fixed = 256.
// W layout: flags&2 ? W[n*ldw + k] (NK) : W[k*ldw + n] (KN).  flags&1: relu.
struct GemmP {
    const float* A1; const float* A2; const float* W; const float* bias; float* C;
    int lda1, K1, lda2, ldw, ldc, Ntiles, K, flags;
};

constexpr int BM = 64, BN = 64, BK = 16;

__global__ __launch_bounds__(256) void gemm2_kernel(GemmP p0, GemmP p1) {
    GemmP p = blockIdx.z ? p1 : p0;
    if ((int)blockIdx.y >= p.Ntiles) return;

    __shared__ float As2[BK][2 * BM];   // A duplicated: As2[k][2m]=As2[k][2m+1]=A[m][k]
    __shared__ float Ws [BK][BN];

    const int tid = threadIdx.x;
    const int m0 = blockIdx.x * BM;
    const int n0 = blockIdx.y * BN;
    const int tx = tid & 15;        // n-dir, TN=4
    const int ty = tid >> 4;        // m-dir, TM=4

    unsigned long long acc[4][2];
#pragma unroll
    for (int i = 0; i < 4; i++) { acc[i][0] = 0ull; acc[i][1] = 0ull; }

    const int arow = tid >> 2;            // 0..63
    const int aseg = (tid & 3) << 2;      // 0,4,8,12
    const bool wNK = (p.flags & 2) != 0;

    for (int kt = 0; kt < p.K; kt += BK) {
        // ---- load A tile (handles concat [A1|A2], A2==null -> zeros) ----
        {
            int kg = kt + aseg;
            int m  = m0 + arow;
            float4 v;
            if (kg < p.K1)      v = *(const float4*)(p.A1 + (long)m * p.lda1 + kg);
            else if (p.A2)      v = *(const float4*)(p.A2 + (long)m * p.lda2 + (kg - p.K1));
            else                v = make_float4(0.f, 0.f, 0.f, 0.f);
            As2[aseg + 0][2*arow] = v.x; As2[aseg + 0][2*arow + 1] = v.x;
            As2[aseg + 1][2*arow] = v.y; As2[aseg + 1][2*arow + 1] = v.y;
            As2[aseg + 2][2*arow] = v.z; As2[aseg + 2][2*arow + 1] = v.z;
            As2[aseg + 3][2*arow] = v.w; As2[aseg + 3][2*arow + 1] = v.w;
        }
        // ---- load W tile ----
        if (wNK) {
            float4 v = *(const float4*)(p.W + (long)(n0 + arow) * p.ldw + kt + aseg);
            Ws[aseg + 0][arow] = v.x; Ws[aseg + 1][arow] = v.y;
            Ws[aseg + 2][arow] = v.z; Ws[aseg + 3][arow] = v.w;
        } else {
            int r = tid >> 4;            // 0..15 (k rows)
            int c = (tid & 15) << 2;     // 0..60
            float4 v = *(const float4*)(p.W + (long)(kt + r) * p.ldw + n0 + c);
            *(float4*)&Ws[r][c] = v;
        }
        __syncthreads();

#pragma unroll
        for (int k = 0; k < BK; k++) {
            ulonglong2 aA = *(const ulonglong2*)&As2[k][8 * ty];
            ulonglong2 aB = *(const ulonglong2*)&As2[k][8 * ty + 4];
            ulonglong2 bv = *(const ulonglong2*)&Ws[k][4 * tx];
            acc[0][0] = ffma2(aA.x, bv.x, acc[0][0]); acc[0][1] = ffma2(aA.x, bv.y, acc[0][1]);
            acc[1][0] = ffma2(aA.y, bv.x, acc[1][0]); acc[1][1] = ffma2(aA.y, bv.y, acc[1][1]);
            acc[2][0] = ffma2(aB.x, bv.x, acc[2][0]); acc[2][1] = ffma2(aB.x, bv.y, acc[2][1]);
            acc[3][0] = ffma2(aB.y, bv.x, acc[3][0]); acc[3][1] = ffma2(aB.y, bv.y, acc[3][1]);
        }
        __syncthreads();
    }

    const bool relu = (p.flags & 1) != 0;
#pragma unroll
    for (int i = 0; i < 4; i++) {
        int m = m0 + 4 * ty + i;
#pragma unroll
        for (int j = 0; j < 2; j++) {
            int n = n0 + 4 * tx + 2 * j;
            float2 c2 = *(float2*)&acc[i][j];
            c2.x += p.bias[n];
            c2.y += p.bias[n + 1];
            if (relu) { c2.x = fmaxf(c2.x, 0.f); c2.y = fmaxf(c2.y, 0.f); }
            *(float2*)(p.C + (long)m * p.ldc + n) = c2;
        }
    }
}

// ---------------- GRU gate combine (PyTorch GRUCell order r,u,n) ----------------
__global__ __launch_bounds__(256) void gru_kernel(float* __restrict__ hout) {
    int idx = blockIdx.x * blockDim.x + threadIdx.x;  // over B*DET/4
    int b = idx >> 9;                // DET/4 = 512
    int d = (idx & 511) << 2;
    const float* gi = g_gi + (long)b * G3 + d;
    const float* gh = g_gh + (long)b * G3 + d;
    float4 ir  = *(const float4*)(gi);
    float4 iu  = *(const float4*)(gi + DETn);
    float4 in_ = *(const float4*)(gi + 2 * DETn);
    float4 hr  = *(const float4*)(gh);
    float4 hu  = *(const float4*)(gh + DETn);
    float4 hn  = *(const float4*)(gh + 2 * DETn);
    float4 hp  = *(const float4*)(g_h + (long)b * DETn + d);
    float4 hs;
#define GRUC(X) { \
    float r = 1.f / (1.f + expf(-(ir.X + hr.X))); \
    float u = 1.f / (1.f + expf(-(iu.X + hu.X))); \
    float n = tanhf(in_.X + r * hn.X);            \
    hs.X = (1.f - u) * n + u * hp.X; }
    GRUC(x) GRUC(y) GRUC(z) GRUC(w)
#undef GRUC
    *(float4*)(g_h + (long)b * DETn + d) = hs;
    *(float4*)(hout + (long)b * (Tt * DETn) + d) = hs;
}

// ---------------- mean/std head: out = Ain @ W + b, split into (mean, softplus(std)+0.1),
// optionally z = mean + std*eps. One launch handles posterior (z=0) + prior (z=1). ----------
struct MsP {
    const float* Ain; const float* W; const float* bias;
    float* out_m; float* out_s; float* out_z; float* z_scr; const float* eps;
};

constexpr int MS_BM = 32, MS_BN = 32, MS_BK = 16;

__global__ __launch_bounds__(256) void ms_kernel(MsP q0, MsP q1) {
    MsP q = blockIdx.z ? q1 : q0;
    __shared__ float As2[MS_BK][2 * MS_BM];
    __shared__ float Wm [MS_BK][MS_BN];
    __shared__ float Wsd[MS_BK][MS_BN];

    const int tid = threadIdx.x;
    const int m0 = blockIdx.x * MS_BM;
    const int n0 = blockIdx.y * MS_BN;
    const int tx = tid & 15;        // n-dir, TN=2
    const int ty = tid >> 4;        // m-dir, TM=2

    unsigned long long am[2] = {0ull, 0ull}, as_[2] = {0ull, 0ull};

    for (int kt = 0; kt < HIDn; kt += MS_BK) {
        if (tid < 128) {
            int arow = tid >> 2, aseg = (tid & 3) << 2;
            float4 v = *(const float4*)(q.Ain + (long)(m0 + arow) * HIDn + kt + aseg);
            As2[aseg + 0][2*arow] = v.x; As2[aseg + 0][2*arow + 1] = v.x;
            As2[aseg + 1][2*arow] = v.y; As2[aseg + 1][2*arow + 1] = v.y;
            As2[aseg + 2][2*arow] = v.z; As2[aseg + 2][2*arow + 1] = v.z;
            As2[aseg + 3][2*arow] = v.w; As2[aseg + 3][2*arow + 1] = v.w;
        } else {
            int t2 = tid - 128;
            int r = t2 >> 3;          // 0..15
            int c = (t2 & 7) << 2;    // 0..28
            const float* wrow = q.W + (long)(kt + r) * (2 * STOn) + n0 + c;
            *(float4*)&Wm [r][c] = *(const float4*)(wrow);
            *(float4*)&Wsd[r][c] = *(const float4*)(wrow + STOn);
        }
        __syncthreads();
#pragma unroll
        for (int k = 0; k < MS_BK; k++) {
            ulonglong2 aa = *(const ulonglong2*)&As2[k][4 * ty];
            unsigned long long bm = *(const unsigned long long*)&Wm [k][2 * tx];
            unsigned long long bs = *(const unsigned long long*)&Wsd[k][2 * tx];
            am [0] = ffma2(aa.x, bm, am [0]); am [1] = ffma2(aa.y, bm, am [1]);
            as_[0] = ffma2(aa.x, bs, as_[0]); as_[1] = ffma2(aa.y, bs, as_[1]);
        }
        __syncthreads();
    }

#pragma unroll
    for (int i = 0; i < 2; i++) {
        int m = m0 + 2 * ty + i;
        float2 mm = *(float2*)&am[i];
        float2 ss = *(float2*)&as_[i];
        long orow = (long)m * (Tt * STOn);
#pragma unroll
        for (int hh = 0; hh < 2; hh++) {
            int n = n0 + 2 * tx + hh;
            float mean = (hh ? mm.y : mm.x) + q.bias[n];
            float spre = (hh ? ss.y : ss.x) + q.bias[n + STOn];
            float sp = (spre > 20.f) ? spre : log1pf(expf(spre));
            float s = sp + 0.1f;
            q.out_m[orow + n] = mean;
            q.out_s[orow + n] = s;
            if (q.out_z) {
                float e = q.eps[orow + n];
                float zv = fmaf(s, e, mean);
                q.out_z[orow + n] = zv;
                q.z_scr[(long)m * STOn + n] = zv;
            }
        }
    }
}

// ---------------- carry init (h0 = z0 = 0; reference zeroes carries regardless of inputs) ----
__global__ void zero_kernel() {
    int idx = blockIdx.x * blockDim.x + threadIdx.x;
    if (idx < Bb * DETn) g_h[idx] = 0.f;
    if (idx < Bb * STOn) g_z[idx] = 0.f;
}

// ---------------- host orchestration (graph-capturable: launches only) ----------------
extern "C" void kernel_launch(void* const* d_in, const int* in_sizes, int n_in,
                              void* d_out, int out_size) {
    const float* obs        = (const float*)d_in[0];
    const float* actions    = (const float*)d_in[1];
    // d_in[2] init_h, d_in[3] init_z are ignored (reference zeroes the carry at t=0)
    const float* noise      = (const float*)d_in[4];
    const float* W_rnn      = (const float*)d_in[5];
    const float* b_rnn      = (const float*)d_in[6];
    const float* Wih        = (const float*)d_in[7];
    const float* Whh        = (const float*)d_in[8];
    const float* bih        = (const float*)d_in[9];
    const float* bhh        = (const float*)d_in[10];
    const float* W_post_in  = (const float*)d_in[11];
    const float* b_post_in  = (const float*)d_in[12];
    const float* W_post_ms  = (const float*)d_in[13];
    const float* b_post_ms  = (const float*)d_in[14];
    const float* W_prior_in = (const float*)d_in[15];
    const float* b_prior_in = (const float*)d_in[16];
    const float* W_prior_ms = (const float*)d_in[17];
    const float* b_prior_ms = (const float*)d_in[18];
    float* out = (float*)d_out;

    float *zp, *hp, *rnnp, *gip, *ghp, *pfp, *rfp;
    cudaGetSymbolAddress((void**)&zp,   g_z);
    cudaGetSymbolAddress((void**)&hp,   g_h);
    cudaGetSymbolAddress((void**)&rnnp, g_rnn);
    cudaGetSymbolAddress((void**)&gip,  g_gi);
    cudaGetSymbolAddress((void**)&ghp,  g_gh);
    cudaGetSymbolAddress((void**)&pfp,  g_pf);
    cudaGetSymbolAddress((void**)&rfp,  g_rf);

    float* out_h  = out;
    float* out_z  = out_h  + (long)Bb * Tt * DETn;
    float* out_pm = out_z  + (long)Bb * Tt * STOn;
    float* out_ps = out_pm + (long)Bb * Tt * STOn;
    float* out_qm = out_ps + (long)Bb * Tt * STOn;
    float* out_qs = out_qm + (long)Bb * Tt * STOn;

    zero_kernel<<<(Bb * DETn) / 256, 256>>>();

    for (int t = 0; t < Tt; t++) {
        // L1: fused [gh | rnn_in]  (both depend only on h_prev / z_prev / a_prev)
        GemmP pgh;
        pgh.A1 = hp;  pgh.A2 = nullptr; pgh.W = Whh; pgh.bias = bhh; pgh.C = ghp;
        pgh.lda1 = DETn; pgh.K1 = DETn; pgh.lda2 = 0; pgh.ldw = DETn; pgh.ldc = G3;
        pgh.Ntiles = G3 / BN; pgh.K = DETn; pgh.flags = 2;  // NK, no relu

        GemmP prnn;
        prnn.A1 = zp; prnn.A2 = (t > 0) ? (actions + (long)(t - 1) * Aa) : nullptr;
        prnn.W = W_rnn; prnn.bias = b_rnn; prnn.C = rnnp;
        prnn.lda1 = STOn; prnn.K1 = STOn; prnn.lda2 = Tt * Aa; prnn.ldw = HIDn;
        prnn.ldc = HIDn; prnn.Ntiles = HIDn / BN; prnn.K = STOn + Aa; prnn.flags = 1; // KN, relu

        gemm2_kernel<<<dim3(Bb / BM, G3 / BN, 2), 256>>>(pgh, prnn);

        // L2: gi = rnn_in @ Wih^T + bih
        GemmP pgi;
        pgi.A1 = rnnp; pgi.A2 = nullptr; pgi.W = Wih; pgi.bias = bih; pgi.C = gip;
        pgi.lda1 = HIDn; pgi.K1 = HIDn; pgi.lda2 = 0; pgi.ldw = HIDn; pgi.ldc = G3;
        pgi.Ntiles = G3 / BN; pgi.K = HIDn; pgi.flags = 2;
        gemm2_kernel<<<dim3(Bb / BM, G3 / BN, 1), 256>>>(pgi, pgi);

        // L3: GRU elementwise -> h (scratch + h_seq output)
        gru_kernel<<<(Bb * DETn / 4) / 256, 256>>>(out_h + (long)t * DETn);

        // L4: fused [post_in | prior_in]
        GemmP ppo;
        ppo.A1 = hp; ppo.A2 = obs + (long)t * Ee; ppo.W = W_post_in; ppo.bias = b_post_in;
        ppo.C = pfp; ppo.lda1 = DETn; ppo.K1 = DETn; ppo.lda2 = Tt * Ee; ppo.ldw = HIDn;
        ppo.ldc = HIDn; ppo.Ntiles = HIDn / BN; ppo.K = DETn + Ee; ppo.flags = 1;

        GemmP ppr;
        ppr.A1 = hp; ppr.A2 = nullptr; ppr.W = W_prior_in; ppr.bias = b_prior_in;
        ppr.C = rfp; ppr.lda1 = DETn; ppr.K1 = DETn; ppr.lda2 = 0; ppr.ldw = HIDn;
        ppr.ldc = HIDn; ppr.Ntiles = HIDn / BN; ppr.K = DETn; ppr.flags = 1;

        gemm2_kernel<<<dim3(Bb / BM, HIDn / BN, 2), 256>>>(ppo, ppr);

        // L5: fused mean/std heads (posterior writes pm/ps/z + z carry; prior writes qm/qs)
        MsP qpost;
        qpost.Ain = pfp; qpost.W = W_post_ms; qpost.bias = b_post_ms;
        qpost.out_m = out_pm + (long)t * STOn; qpost.out_s = out_ps + (long)t * STOn;
        qpost.out_z = out_z + (long)t * STOn; qpost.z_scr = zp;
        qpost.eps = noise + (long)t * STOn;

        MsP qpri;
        qpri.Ain = rfp; qpri.W = W_prior_ms; qpri.bias = b_prior_ms;
        qpri.out_m = out_qm + (long)t * STOn; qpri.out_s = out_qs + (long)t * STOn;
        qpri.out_z = nullptr; qpri.z_scr = nullptr; qpri.eps = nullptr;

        ms_kernel<<<dim3(Bb / MS_BM, STOn / MS_BN, 2), 256>>>(qpost, qpri);
    }
}

// round 4
// speedup vs baseline: 3.4483x; 3.4483x over previous
#include <cuda_runtime.h>
#include <cuda_bf16.h>
#include <math.h>
#include <stdint.h>

// ---------------- problem constants ----------------
constexpr int Bb  = 256;
constexpr int Tt  = 64;
constexpr int Aa  = 64;
constexpr int Ee  = 1024;
constexpr int HIDn = 1024;
constexpr int DETn = 2048;
constexpr int STOn = 256;
constexpr int G3  = 3 * DETn;   // 6144

typedef __nv_bfloat16 bf16;

// ---------------- device-global scratch (no allocation allowed) ----------------
// __align__(256): cp.async/vector accesses require >= 16B alignment; type alignment
// alone (2B for bf16) is NOT guaranteed sufficient.
__device__ __align__(256) bf16 g_Bhh_hi [G3 * DETn],  g_Bhh_lo [G3 * DETn];
__device__ __align__(256) bf16 g_Bih_hi [G3 * HIDn],  g_Bih_lo [G3 * HIDn];
__device__ __align__(256) bf16 g_Brnn_hi[HIDn * 320], g_Brnn_lo[HIDn * 320];
__device__ __align__(256) bf16 g_Bpo_hi [HIDn * 3072],g_Bpo_lo [HIDn * 3072];
__device__ __align__(256) bf16 g_Bpr_hi [HIDn * DETn],g_Bpr_lo [HIDn * DETn];
__device__ __align__(256) bf16 g_Bpm_hi [512 * HIDn], g_Bpm_lo [512 * HIDn];
__device__ __align__(256) bf16 g_Bqm_hi [512 * HIDn], g_Bqm_lo [512 * HIDn];
__device__ __align__(256) bf16 g_obs_hi[Bb * Tt * Ee], g_obs_lo[Bb * Tt * Ee];
__device__ __align__(256) bf16 g_act_hi[Bb * Tt * Aa], g_act_lo[Bb * Tt * Aa];
__device__ __align__(256) bf16 g_zact  [Bb * Aa];      // stays zero
__device__ __align__(256) float g_h   [Bb * DETn];
__device__ __align__(256) bf16  g_h_hi[Bb * DETn], g_h_lo[Bb * DETn];
__device__ __align__(256) bf16  g_z_hi[Bb * STOn], g_z_lo[Bb * STOn];
__device__ __align__(256) bf16  g_rn_hi[Bb * HIDn], g_rn_lo[Bb * HIDn];
__device__ __align__(256) bf16  g_pf_hi[Bb * HIDn], g_pf_lo[Bb * HIDn];
__device__ __align__(256) bf16  g_rf_hi[Bb * HIDn], g_rf_lo[Bb * HIDn];
__device__ __align__(256) float g_gi[Bb * G3], g_gh[Bb * G3];
__device__ __align__(256) float g_ms_p[Bb * 512], g_ms_q[Bb * 512];

// ---------------- helpers ----------------
__device__ __forceinline__ uint32_t smem_u32(const void* p) {
    uint32_t a;
    asm("{ .reg .u64 t; cvta.to.shared.u64 t, %1; cvt.u32.u64 %0, t; }" : "=r"(a) : "l"(p));
    return a;
}
__device__ __forceinline__ void cpa16(uint32_t dst, const void* src) {
    asm volatile("cp.async.cg.shared.global [%0], [%1], 16;" :: "r"(dst), "l"(src) : "memory");
}
__device__ __forceinline__ void ldsm4(uint32_t& r0, uint32_t& r1, uint32_t& r2, uint32_t& r3,
                                      uint32_t a) {
    asm volatile("ldmatrix.sync.aligned.m8n8.x4.shared.b16 {%0,%1,%2,%3}, [%4];"
                 : "=r"(r0), "=r"(r1), "=r"(r2), "=r"(r3) : "r"(a));
}
__device__ __forceinline__ void mmabf(float* c, const uint32_t* a, const uint32_t* b) {
    asm volatile(
        "mma.sync.aligned.m16n8k16.row.col.f32.bf16.bf16.f32 "
        "{%0,%1,%2,%3}, {%4,%5,%6,%7}, {%8,%9}, {%0,%1,%2,%3};"
        : "+f"(c[0]), "+f"(c[1]), "+f"(c[2]), "+f"(c[3])
        : "r"(a[0]), "r"(a[1]), "r"(a[2]), "r"(a[3]), "r"(b[0]), "r"(b[1]));
}
__device__ __forceinline__ void split2(float v, bf16& h, bf16& l) {
    h = __float2bfloat16(v);
    l = __float2bfloat16(v - __bfloat162float(h));
}

// ---------------- tensor GEMM: C[256,N] = epi([A1|A2] @ B^T + bias), 3-term bf16 split ----
struct TG {
    const bf16 *A1hi, *A1lo, *A2hi, *A2lo;
    const bf16 *Bhi, *Blo;
    const float* bias;
    float* C;            // epi 0
    bf16 *Chi, *Clo;     // epi 1
    long lda1, lda2, ldb;
    int K1, K, Ntiles, ldc, ldch, epi;
};

constexpr int ROW_B  = 80;               // padded smem row (bytes) for 32 bf16
constexpr int A_PART = 128 * ROW_B;      // 10240
constexpr int B_PART = 64 * ROW_B;       // 5120
constexpr int STAGE  = 2 * A_PART + 2 * B_PART;   // Ah, Al, Bh, Bl = 30720
constexpr int SMEM_TOTAL = 2 * STAGE;             // 61440

__global__ __launch_bounds__(256, 2) void tgemm_kernel(TG p0, TG p1) {
    TG p = blockIdx.z ? p1 : p0;
    if ((int)blockIdx.y >= p.Ntiles) return;

    extern __shared__ char smem[];
    const uint32_t sb = smem_u32(smem);
    const int tid = threadIdx.x, wid = tid >> 5, lane = tid & 31;
    const int m0 = blockIdx.x * 128, n0 = blockIdx.y * 64;
    const int wm = (wid & 3) * 32, wn = (wid >> 2) * 32;

    auto loadChunk = [&](int c) {
        uint32_t stg = sb + (c & 1) * STAGE;
        long koff = (long)c * 32;
        const bf16 *ah, *al; long lda;
        if (koff < p.K1) { ah = p.A1hi; al = p.A1lo; lda = p.lda1; }
        else             { ah = p.A2hi; al = p.A2lo; lda = p.lda2; koff -= p.K1; }
        const bf16* a_hi = ah + (long)m0 * lda + koff;
        const bf16* a_lo = al + (long)m0 * lda + koff;
        const bf16* b_hi = p.Bhi + (long)n0 * p.ldb + (long)c * 32;
        const bf16* b_lo = p.Blo + (long)n0 * p.ldb + (long)c * 32;
#pragma unroll
        for (int o = tid; o < 512; o += 256) {
            int row = o >> 2, seg = o & 3;
            cpa16(stg + row * ROW_B + seg * 16,          a_hi + (long)row * lda + seg * 8);
            cpa16(stg + A_PART + row * ROW_B + seg * 16, a_lo + (long)row * lda + seg * 8);
        }
        {
            int row = tid >> 2, seg = tid & 3;
            cpa16(stg + 2 * A_PART + row * ROW_B + seg * 16,
                  b_hi + (long)row * p.ldb + seg * 8);
            cpa16(stg + 2 * A_PART + B_PART + row * ROW_B + seg * 16,
                  b_lo + (long)row * p.ldb + seg * 8);
        }
        asm volatile("cp.async.commit_group;" ::: "memory");
    };

    float acc[2][4][4];
#pragma unroll
    for (int i = 0; i < 2; i++)
#pragma unroll
        for (int j = 0; j < 4; j++)
#pragma unroll
            for (int k = 0; k < 4; k++) acc[i][j][k] = 0.f;

    const int nch = p.K >> 5;
    loadChunk(0);
    for (int c = 0; c < nch; c++) {
        if (c + 1 < nch) {
            loadChunk(c + 1);
            asm volatile("cp.async.wait_group 1;" ::: "memory");
        } else {
            asm volatile("cp.async.wait_group 0;" ::: "memory");
        }
        __syncthreads();

        const uint32_t stg = sb + (c & 1) * STAGE;
#pragma unroll
        for (int kk = 0; kk < 2; kk++) {
            uint32_t Ah[2][4], Al[2][4], Bh[2][4], Bl[2][4];
#pragma unroll
            for (int mi = 0; mi < 2; mi++) {
                int row = wm + 16 * mi + (lane & 15);
                uint32_t ad = stg + row * ROW_B + kk * 32 + ((lane >> 4) << 4);
                ldsm4(Ah[mi][0], Ah[mi][1], Ah[mi][2], Ah[mi][3], ad);
                ldsm4(Al[mi][0], Al[mi][1], Al[mi][2], Al[mi][3], ad + A_PART);
            }
#pragma unroll
            for (int pp = 0; pp < 2; pp++) {
                int row = wn + 16 * pp + ((lane >> 4) << 3) + (lane & 7);
                uint32_t bd = stg + 2 * A_PART + row * ROW_B + kk * 32 + (((lane >> 3) & 1) << 4);
                ldsm4(Bh[pp][0], Bh[pp][1], Bh[pp][2], Bh[pp][3], bd);
                ldsm4(Bl[pp][0], Bl[pp][1], Bl[pp][2], Bl[pp][3], bd + B_PART);
            }
#pragma unroll
            for (int mi = 0; mi < 2; mi++)
#pragma unroll
                for (int pp = 0; pp < 2; pp++)
#pragma unroll
                    for (int tt = 0; tt < 2; tt++) {
                        float* ca = acc[mi][2 * pp + tt];
                        mmabf(ca, Ah[mi], &Bh[pp][2 * tt]);
                        mmabf(ca, Ah[mi], &Bl[pp][2 * tt]);
                        mmabf(ca, Al[mi], &Bh[pp][2 * tt]);
                    }
        }
        __syncthreads();
    }

    // ---- epilogue ----
    const int mg = m0 + wm, ng = n0 + wn;
#pragma unroll
    for (int mi = 0; mi < 2; mi++) {
        int r = mg + 16 * mi + (lane >> 2);
#pragma unroll
        for (int nj = 0; nj < 4; nj++) {
            int cg = ng + 8 * nj + 2 * (lane & 3);
            float b0 = p.bias[cg], b1 = p.bias[cg + 1];
            float v00 = acc[mi][nj][0] + b0, v01 = acc[mi][nj][1] + b1;
            float v10 = acc[mi][nj][2] + b0, v11 = acc[mi][nj][3] + b1;
            if (p.epi == 1) {
                v00 = fmaxf(v00, 0.f); v01 = fmaxf(v01, 0.f);
                v10 = fmaxf(v10, 0.f); v11 = fmaxf(v11, 0.f);
                __nv_bfloat162 h2, l2;
                split2(v00, h2.x, l2.x); split2(v01, h2.y, l2.y);
                *(__nv_bfloat162*)(p.Chi + (long)r * p.ldch + cg) = h2;
                *(__nv_bfloat162*)(p.Clo + (long)r * p.ldch + cg) = l2;
                split2(v10, h2.x, l2.x); split2(v11, h2.y, l2.y);
                *(__nv_bfloat162*)(p.Chi + (long)(r + 8) * p.ldch + cg) = h2;
                *(__nv_bfloat162*)(p.Clo + (long)(r + 8) * p.ldch + cg) = l2;
            } else {
                float2 f2;
                f2.x = v00; f2.y = v01;
                *(float2*)(p.C + (long)r * p.ldc + cg) = f2;
                f2.x = v10; f2.y = v11;
                *(float2*)(p.C + (long)(r + 8) * p.ldc + cg) = f2;
            }
        }
    }
}

// ---------------- GRU gate combine ----------------
__global__ __launch_bounds__(256) void gru_kernel(float* __restrict__ hout) {
    int idx = blockIdx.x * blockDim.x + threadIdx.x;
    int b = idx >> 9;
    int d = (idx & 511) << 2;
    const float* gi = g_gi + (long)b * G3 + d;
    const float* gh = g_gh + (long)b * G3 + d;
    float4 ir  = *(const float4*)(gi);
    float4 iu  = *(const float4*)(gi + DETn);
    float4 in_ = *(const float4*)(gi + 2 * DETn);
    float4 hr  = *(const float4*)(gh);
    float4 hu  = *(const float4*)(gh + DETn);
    float4 hn  = *(const float4*)(gh + 2 * DETn);
    float4 hp  = *(const float4*)(g_h + (long)b * DETn + d);
    float4 hs;
#define GRUC(X) { \
    float r = 1.f / (1.f + expf(-(ir.X + hr.X))); \
    float u = 1.f / (1.f + expf(-(iu.X + hu.X))); \
    float n = tanhf(in_.X + r * hn.X);            \
    hs.X = (1.f - u) * n + u * hp.X; }
    GRUC(x) GRUC(y) GRUC(z) GRUC(w)
#undef GRUC
    *(float4*)(g_h + (long)b * DETn + d) = hs;
    *(float4*)(hout + (long)b * (Tt * DETn) + d) = hs;
    long o = (long)b * DETn + d;
#pragma unroll
    for (int j = 0; j < 4; j++) {
        float v = (&hs.x)[j];
        split2(v, g_h_hi[o + j], g_h_lo[o + j]);
    }
}

// ---------------- ms-head finalize ----------------
__device__ __forceinline__ float softplusf(float x) {
    return (x > 20.f) ? x : log1pf(expf(x));
}
__global__ __launch_bounds__(256) void combine_kernel(
    const float* __restrict__ eps, float* pm_o, float* ps_o, float* z_o,
    float* qm_o, float* qs_o) {
    int i = blockIdx.x * 256 + threadIdx.x;
    int b = i >> 8, n = i & 255;
    long o = (long)b * (Tt * STOn) + n;
    float m  = g_ms_p[b * 512 + n];
    float ls = g_ms_p[b * 512 + 256 + n];
    float s  = softplusf(ls) + 0.1f;
    float z  = fmaf(s, eps[o], m);
    pm_o[o] = m; ps_o[o] = s; z_o[o] = z;
    split2(z, g_z_hi[b * 256 + n], g_z_lo[b * 256 + n]);
    float qm  = g_ms_q[b * 512 + n];
    float qls = g_ms_q[b * 512 + 256 + n];
    qm_o[o] = qm; qs_o[o] = softplusf(qls) + 0.1f;
}

// ---------------- prep kernels ----------------
__global__ void split_kernel(const float* __restrict__ src, bf16* hi, bf16* lo, int n) {
    for (int i = blockIdx.x * blockDim.x + threadIdx.x; i < n; i += gridDim.x * blockDim.x) {
        split2(src[i], hi[i], lo[i]);
    }
}
__global__ void tsplit_kernel(const float* __restrict__ src, bf16* dhi, bf16* dlo, int R, int C) {
    __shared__ float t[32][33];
    int c0 = blockIdx.x * 32, r0 = blockIdx.y * 32;
    int tx = threadIdx.x, ty = threadIdx.y;
    for (int i = ty; i < 32; i += 8)
        t[i][tx] = src[(long)(r0 + i) * C + c0 + tx];
    __syncthreads();
    for (int i = ty; i < 32; i += 8) {
        float v = t[tx][i];
        long o = (long)(c0 + i) * R + r0 + tx;
        split2(v, dhi[o], dlo[o]);
    }
}
__global__ void zero_kernel() {
    int i = blockIdx.x * blockDim.x + threadIdx.x;
    if (i < Bb * DETn) {
        g_h[i] = 0.f;
        g_h_hi[i] = __float2bfloat16(0.f);
        g_h_lo[i] = __float2bfloat16(0.f);
    }
    if (i < Bb * STOn) {
        g_z_hi[i] = __float2bfloat16(0.f);
        g_z_lo[i] = __float2bfloat16(0.f);
    }
}

// ---------------- host orchestration ----------------
static void* sym(const void* s) { void* p; cudaGetSymbolAddress(&p, s); return p; }

extern "C" void kernel_launch(void* const* d_in, const int* in_sizes, int n_in,
                              void* d_out, int out_size) {
    const float* obs        = (const float*)d_in[0];
    const float* actions    = (const float*)d_in[1];
    const float* noise      = (const float*)d_in[4];
    const float* W_rnn      = (const float*)d_in[5];
    const float* b_rnn      = (const float*)d_in[6];
    const float* Wih        = (const float*)d_in[7];
    const float* Whh        = (const float*)d_in[8];
    const float* bih        = (const float*)d_in[9];
    const float* bhh        = (const float*)d_in[10];
    const float* W_post_in  = (const float*)d_in[11];
    const float* b_post_in  = (const float*)d_in[12];
    const float* W_post_ms  = (const float*)d_in[13];
    const float* b_post_ms  = (const float*)d_in[14];
    const float* W_prior_in = (const float*)d_in[15];
    const float* b_prior_in = (const float*)d_in[16];
    const float* W_prior_ms = (const float*)d_in[17];
    const float* b_prior_ms = (const float*)d_in[18];
    float* out = (float*)d_out;

    cudaFuncSetAttribute(tgemm_kernel, cudaFuncAttributeMaxDynamicSharedMemorySize, SMEM_TOTAL);

    bf16 *Bhh_hi = (bf16*)sym(g_Bhh_hi), *Bhh_lo = (bf16*)sym(g_Bhh_lo);
    bf16 *Bih_hi = (bf16*)sym(g_Bih_hi), *Bih_lo = (bf16*)sym(g_Bih_lo);
    bf16 *Brnn_hi = (bf16*)sym(g_Brnn_hi), *Brnn_lo = (bf16*)sym(g_Brnn_lo);
    bf16 *Bpo_hi = (bf16*)sym(g_Bpo_hi), *Bpo_lo = (bf16*)sym(g_Bpo_lo);
    bf16 *Bpr_hi = (bf16*)sym(g_Bpr_hi), *Bpr_lo = (bf16*)sym(g_Bpr_lo);
    bf16 *Bpm_hi = (bf16*)sym(g_Bpm_hi), *Bpm_lo = (bf16*)sym(g_Bpm_lo);
    bf16 *Bqm_hi = (bf16*)sym(g_Bqm_hi), *Bqm_lo = (bf16*)sym(g_Bqm_lo);
    bf16 *obs_hi = (bf16*)sym(g_obs_hi), *obs_lo = (bf16*)sym(g_obs_lo);
    bf16 *act_hi = (bf16*)sym(g_act_hi), *act_lo = (bf16*)sym(g_act_lo);
    bf16 *zact   = (bf16*)sym(g_zact);
    bf16 *h_hi = (bf16*)sym(g_h_hi), *h_lo = (bf16*)sym(g_h_lo);
    bf16 *z_hi = (bf16*)sym(g_z_hi), *z_lo = (bf16*)sym(g_z_lo);
    bf16 *rn_hi = (bf16*)sym(g_rn_hi), *rn_lo = (bf16*)sym(g_rn_lo);
    bf16 *pf_hi = (bf16*)sym(g_pf_hi), *pf_lo = (bf16*)sym(g_pf_lo);
    bf16 *rf_hi = (bf16*)sym(g_rf_hi), *rf_lo = (bf16*)sym(g_rf_lo);
    float *gi_p = (float*)sym(g_gi), *gh_p = (float*)sym(g_gh);
    float *msp = (float*)sym(g_ms_p), *msq = (float*)sym(g_ms_q);

    float* out_h  = out;
    float* out_z  = out_h  + (long)Bb * Tt * DETn;
    float* out_pm = out_z  + (long)Bb * Tt * STOn;
    float* out_ps = out_pm + (long)Bb * Tt * STOn;
    float* out_qm = out_ps + (long)Bb * Tt * STOn;
    float* out_qs = out_qm + (long)Bb * Tt * STOn;

    // ---- prep: zero carry, split/transpose weights + constant activations ----
    zero_kernel<<<(Bb * DETn) / 256, 256>>>();
    split_kernel<<<4096, 256>>>(Whh, Bhh_hi, Bhh_lo, G3 * DETn);
    split_kernel<<<4096, 256>>>(Wih, Bih_hi, Bih_lo, G3 * HIDn);
    split_kernel<<<4096, 256>>>(obs, obs_hi, obs_lo, Bb * Tt * Ee);
    split_kernel<<<1024, 256>>>(actions, act_hi, act_lo, Bb * Tt * Aa);
    tsplit_kernel<<<dim3(HIDn / 32, 320 / 32),  dim3(32, 8)>>>(W_rnn,      Brnn_hi, Brnn_lo, 320,  HIDn);
    tsplit_kernel<<<dim3(HIDn / 32, 3072 / 32), dim3(32, 8)>>>(W_post_in,  Bpo_hi,  Bpo_lo,  3072, HIDn);
    tsplit_kernel<<<dim3(HIDn / 32, DETn / 32), dim3(32, 8)>>>(W_prior_in, Bpr_hi,  Bpr_lo,  DETn, HIDn);
    tsplit_kernel<<<dim3(512 / 32, HIDn / 32),  dim3(32, 8)>>>(W_post_ms,  Bpm_hi,  Bpm_lo,  HIDn, 512);
    tsplit_kernel<<<dim3(512 / 32, HIDn / 32),  dim3(32, 8)>>>(W_prior_ms, Bqm_hi,  Bqm_lo,  HIDn, 512);

    for (int t = 0; t < Tt; t++) {
        // L1: rnn_in = relu([z_prev | a_prev] @ W_rnn + b) -> rn hi/lo
        TG prnn = {};
        prnn.A1hi = z_hi; prnn.A1lo = z_lo; prnn.lda1 = STOn; prnn.K1 = STOn;
        if (t > 0) { prnn.A2hi = act_hi + (long)(t - 1) * Aa; prnn.A2lo = act_lo + (long)(t - 1) * Aa; prnn.lda2 = (long)Tt * Aa; }
        else       { prnn.A2hi = zact; prnn.A2lo = zact; prnn.lda2 = Aa; }
        prnn.Bhi = Brnn_hi; prnn.Blo = Brnn_lo; prnn.ldb = 320;
        prnn.bias = b_rnn; prnn.K = 320; prnn.Ntiles = HIDn / 64;
        prnn.epi = 1; prnn.Chi = rn_hi; prnn.Clo = rn_lo; prnn.ldch = HIDn;
        tgemm_kernel<<<dim3(2, HIDn / 64, 1), 256, SMEM_TOTAL>>>(prnn, prnn);

        // L2: z0: gh = h @ Whh^T + bhh ; z1: gi = rnn @ Wih^T + bih  (fp32 out)
        TG pgh = {};
        pgh.A1hi = h_hi; pgh.A1lo = h_lo; pgh.lda1 = DETn; pgh.K1 = DETn;
        pgh.Bhi = Bhh_hi; pgh.Blo = Bhh_lo; pgh.ldb = DETn;
        pgh.bias = bhh; pgh.K = DETn; pgh.Ntiles = G3 / 64;
        pgh.epi = 0; pgh.C = gh_p; pgh.ldc = G3;
        TG pgi = {};
        pgi.A1hi = rn_hi; pgi.A1lo = rn_lo; pgi.lda1 = HIDn; pgi.K1 = HIDn;
        pgi.Bhi = Bih_hi; pgi.Blo = Bih_lo; pgi.ldb = HIDn;
        pgi.bias = bih; pgi.K = HIDn; pgi.Ntiles = G3 / 64;
        pgi.epi = 0; pgi.C = gi_p; pgi.ldc = G3;
        tgemm_kernel<<<dim3(2, G3 / 64, 2), 256, SMEM_TOTAL>>>(pgh, pgi);

        // L3: GRU elementwise -> h (fp32 + hi/lo + h_seq output)
        gru_kernel<<<(Bb * DETn / 4) / 256, 256>>>(out_h + (long)t * DETn);

        // L4: z0: pf = relu([h|obs] @ Wpost_in + b) ; z1: rf = relu(h @ Wprior_in + b)
        TG ppo = {};
        ppo.A1hi = h_hi; ppo.A1lo = h_lo; ppo.lda1 = DETn; ppo.K1 = DETn;
        ppo.A2hi = obs_hi + (long)t * Ee; ppo.A2lo = obs_lo + (long)t * Ee; ppo.lda2 = (long)Tt * Ee;
        ppo.Bhi = Bpo_hi; ppo.Blo = Bpo_lo; ppo.ldb = 3072;
        ppo.bias = b_post_in; ppo.K = 3072; ppo.Ntiles = HIDn / 64;
        ppo.epi = 1; ppo.Chi = pf_hi; ppo.Clo = pf_lo; ppo.ldch = HIDn;
        TG ppr = {};
        ppr.A1hi = h_hi; ppr.A1lo = h_lo; ppr.lda1 = DETn; ppr.K1 = DETn;
        ppr.Bhi = Bpr_hi; ppr.Blo = Bpr_lo; ppr.ldb = DETn;
        ppr.bias = b_prior_in; ppr.K = DETn; ppr.Ntiles = HIDn / 64;
        ppr.epi = 1; ppr.Chi = rf_hi; ppr.Clo = rf_lo; ppr.ldch = HIDn;
        tgemm_kernel<<<dim3(2, HIDn / 64, 2), 256, SMEM_TOTAL>>>(ppo, ppr);

        // L5: z0: ms_post = pf @ Wpm^T + b ; z1: ms_prior = rf @ Wqm^T + b (fp32 raw)
        TG qpm = {};
        qpm.A1hi = pf_hi; qpm.A1lo = pf_lo; qpm.lda1 = HIDn; qpm.K1 = HIDn;
        qpm.Bhi = Bpm_hi; qpm.Blo = Bpm_lo; qpm.ldb = HIDn;
        qpm.bias = b_post_ms; qpm.K = HIDn; qpm.Ntiles = 512 / 64;
        qpm.epi = 0; qpm.C = msp; qpm.ldc = 512;
        TG qqm = {};
        qqm.A1hi = rf_hi; qqm.A1lo = rf_lo; qqm.lda1 = HIDn; qqm.K1 = HIDn;
        qqm.Bhi = Bqm_hi; qqm.Blo = Bqm_lo; qqm.ldb = HIDn;
        qqm.bias = b_prior_ms; qqm.K = HIDn; qqm.Ntiles = 512 / 64;
        qqm.epi = 0; qqm.C = msq; qqm.ldc = 512;
        tgemm_kernel<<<dim3(2, 512 / 64, 2), 256, SMEM_TOTAL>>>(qpm, qqm);

        // L6: finalize heads, rsample z, split z to bf16
        combine_kernel<<<256, 256>>>(noise + (long)t * STOn,
                                     out_pm + (long)t * STOn, out_ps + (long)t * STOn,
                                     out_z + (long)t * STOn,
                                     out_qm + (long)t * STOn, out_qs + (long)t * STOn);
    }
}

// round 5
// speedup vs baseline: 4.4407x; 1.2878x over previous
#include <cuda_runtime.h>
#include <cuda_bf16.h>
#include <math.h>
#include <stdint.h>

// ---------------- problem constants ----------------
constexpr int Bb  = 256;
constexpr int Tt  = 64;
constexpr int Aa  = 64;
constexpr int Ee  = 1024;
constexpr int HIDn = 1024;
constexpr int DETn = 2048;
constexpr int STOn = 256;
constexpr int G3  = 3 * DETn;   // 6144

typedef __nv_bfloat16 bf16;

// ---------------- device-global scratch (no allocation allowed) ----------------
__device__ __align__(256) bf16 g_Bhh_hi [G3 * DETn],  g_Bhh_lo [G3 * DETn];
__device__ __align__(256) bf16 g_Bih_hi [G3 * HIDn],  g_Bih_lo [G3 * HIDn];
__device__ __align__(256) bf16 g_Brnn_hi[HIDn * 320], g_Brnn_lo[HIDn * 320];
__device__ __align__(256) bf16 g_Bpo_hi [HIDn * 3072],g_Bpo_lo [HIDn * 3072];
__device__ __align__(256) bf16 g_Bpr_hi [HIDn * DETn],g_Bpr_lo [HIDn * DETn];
__device__ __align__(256) bf16 g_Bpm_hi [512 * HIDn], g_Bpm_lo [512 * HIDn];
__device__ __align__(256) bf16 g_Bqm_hi [512 * HIDn], g_Bqm_lo [512 * HIDn];
__device__ __align__(256) bf16 g_obs_hi[Bb * Tt * Ee], g_obs_lo[Bb * Tt * Ee];
__device__ __align__(256) bf16 g_act_hi[Bb * Tt * Aa], g_act_lo[Bb * Tt * Aa];
__device__ __align__(256) bf16 g_zact  [Bb * Aa];      // stays zero
__device__ __align__(256) float g_h   [Bb * DETn];
__device__ __align__(256) bf16  g_h_hi[Bb * DETn], g_h_lo[Bb * DETn];
__device__ __align__(256) bf16  g_z_hi[Bb * STOn], g_z_lo[Bb * STOn];
__device__ __align__(256) bf16  g_rn_hi[Bb * HIDn], g_rn_lo[Bb * HIDn];
__device__ __align__(256) bf16  g_pf_hi[Bb * HIDn], g_pf_lo[Bb * HIDn];
__device__ __align__(256) bf16  g_rf_hi[Bb * HIDn], g_rf_lo[Bb * HIDn];
__device__ __align__(256) float g_gi[Bb * G3], g_gh[Bb * G3];
__device__ __align__(256) float g_ms_p[Bb * 512], g_ms_q[Bb * 512];

// ---------------- helpers ----------------
__device__ __forceinline__ uint32_t smem_u32(const void* p) {
    uint32_t a;
    asm("{ .reg .u64 t; cvta.to.shared.u64 t, %1; cvt.u32.u64 %0, t; }" : "=r"(a) : "l"(p));
    return a;
}
__device__ __forceinline__ void cpa16(uint32_t dst, const void* src) {
    asm volatile("cp.async.cg.shared.global [%0], [%1], 16;" :: "r"(dst), "l"(src) : "memory");
}
__device__ __forceinline__ void ldsm4(uint32_t& r0, uint32_t& r1, uint32_t& r2, uint32_t& r3,
                                      uint32_t a) {
    asm volatile("ldmatrix.sync.aligned.m8n8.x4.shared.b16 {%0,%1,%2,%3}, [%4];"
                 : "=r"(r0), "=r"(r1), "=r"(r2), "=r"(r3) : "r"(a));
}
__device__ __forceinline__ void mmabf(float* c, const uint32_t* a, const uint32_t* b) {
    asm volatile(
        "mma.sync.aligned.m16n8k16.row.col.f32.bf16.bf16.f32 "
        "{%0,%1,%2,%3}, {%4,%5,%6,%7}, {%8,%9}, {%0,%1,%2,%3};"
        : "+f"(c[0]), "+f"(c[1]), "+f"(c[2]), "+f"(c[3])
        : "r"(a[0]), "r"(a[1]), "r"(a[2]), "r"(a[3]), "r"(b[0]), "r"(b[1]));
}
__device__ __forceinline__ void split2(float v, bf16& h, bf16& l) {
    h = __float2bfloat16(v);
    l = __float2bfloat16(v - __bfloat162float(h));
}

// ---------------- tensor GEMM: C[256,N] = epi([A1|A2] @ B^T + bias), 3-term bf16 split ----
struct TG {
    const bf16 *A1hi, *A1lo, *A2hi, *A2lo;
    const bf16 *Bhi, *Blo;
    const float* bias;
    float* C;            // epi 0
    bf16 *Chi, *Clo;     // epi 1
    long lda1, lda2, ldb;
    int K1, K, Ntiles, ldc, ldch, epi;
};

constexpr int ROW_B = 80;     // padded smem row (bytes) for 32 bf16

template<int BM, int BN, int WRM, int WRN>
__global__ __launch_bounds__(256, 2) void tgemm_kernel(TG p0, TG p1) {
    constexpr int NA = (BM / WRM) / 16;     // A m16 frags per warp
    constexpr int NB = (BN / WRN) / 16;     // B ldsm4 frags per warp (each = 2 n8)
    constexpr int A_PART = BM * ROW_B;
    constexpr int B_PART = BN * ROW_B;
    constexpr int STAGE  = 2 * (A_PART + B_PART);

    TG p = blockIdx.z ? p1 : p0;
    if ((int)blockIdx.y >= p.Ntiles) return;

    extern __shared__ char smem[];
    const uint32_t sb = smem_u32(smem);
    const int tid = threadIdx.x, wid = tid >> 5, lane = tid & 31;
    const int m0 = blockIdx.x * BM, n0 = blockIdx.y * BN;
    const int wm = (wid % WRM) * (BM / WRM), wn = (wid / WRM) * (BN / WRN);

    auto loadChunk = [&](int c) {
        uint32_t stg = sb + (c & 1) * STAGE;
        long koff = (long)c * 32;
        const bf16 *ah, *al; long lda;
        if (koff < p.K1) { ah = p.A1hi; al = p.A1lo; lda = p.lda1; }
        else             { ah = p.A2hi; al = p.A2lo; lda = p.lda2; koff -= p.K1; }
        const bf16* a_hi = ah + (long)m0 * lda + koff;
        const bf16* a_lo = al + (long)m0 * lda + koff;
        const bf16* b_hi = p.Bhi + (long)n0 * p.ldb + (long)c * 32;
        const bf16* b_lo = p.Blo + (long)n0 * p.ldb + (long)c * 32;
#pragma unroll
        for (int o = tid; o < (BM + BN) * 4; o += 256) {
            int row = o >> 2, seg = o & 3;
            if (row < BM) {
                cpa16(stg + row * ROW_B + seg * 16,          a_hi + (long)row * lda + seg * 8);
                cpa16(stg + A_PART + row * ROW_B + seg * 16, a_lo + (long)row * lda + seg * 8);
            } else {
                int br = row - BM;
                cpa16(stg + 2 * A_PART + br * ROW_B + seg * 16,
                      b_hi + (long)br * p.ldb + seg * 8);
                cpa16(stg + 2 * A_PART + B_PART + br * ROW_B + seg * 16,
                      b_lo + (long)br * p.ldb + seg * 8);
            }
        }
        asm volatile("cp.async.commit_group;" ::: "memory");
    };

    float acc[NA][2 * NB][4];
#pragma unroll
    for (int i = 0; i < NA; i++)
#pragma unroll
        for (int j = 0; j < 2 * NB; j++)
#pragma unroll
            for (int k = 0; k < 4; k++) acc[i][j][k] = 0.f;

    const int nch = p.K >> 5;
    loadChunk(0);
    for (int c = 0; c < nch; c++) {
        if (c + 1 < nch) {
            loadChunk(c + 1);
            asm volatile("cp.async.wait_group 1;" ::: "memory");
        } else {
            asm volatile("cp.async.wait_group 0;" ::: "memory");
        }
        __syncthreads();

        const uint32_t stg = sb + (c & 1) * STAGE;
#pragma unroll
        for (int kk = 0; kk < 2; kk++) {
            uint32_t Ah[NA][4], Al[NA][4], Bh[NB][4], Bl[NB][4];
#pragma unroll
            for (int mi = 0; mi < NA; mi++) {
                int row = wm + 16 * mi + (lane & 15);
                uint32_t ad = stg + row * ROW_B + kk * 32 + ((lane >> 4) << 4);
                ldsm4(Ah[mi][0], Ah[mi][1], Ah[mi][2], Ah[mi][3], ad);
                ldsm4(Al[mi][0], Al[mi][1], Al[mi][2], Al[mi][3], ad + A_PART);
            }
#pragma unroll
            for (int pp = 0; pp < NB; pp++) {
                int row = wn + 16 * pp + ((lane >> 4) << 3) + (lane & 7);
                uint32_t bd = stg + 2 * A_PART + row * ROW_B + kk * 32 + (((lane >> 3) & 1) << 4);
                ldsm4(Bh[pp][0], Bh[pp][1], Bh[pp][2], Bh[pp][3], bd);
                ldsm4(Bl[pp][0], Bl[pp][1], Bl[pp][2], Bl[pp][3], bd + B_PART);
            }
#pragma unroll
            for (int mi = 0; mi < NA; mi++)
#pragma unroll
                for (int pp = 0; pp < NB; pp++)
#pragma unroll
                    for (int tt = 0; tt < 2; tt++) {
                        float* ca = acc[mi][2 * pp + tt];
                        mmabf(ca, Ah[mi], &Bh[pp][2 * tt]);
                        mmabf(ca, Ah[mi], &Bl[pp][2 * tt]);
                        mmabf(ca, Al[mi], &Bh[pp][2 * tt]);
                    }
        }
        __syncthreads();
    }

    // ---- epilogue ----
    const int mg = m0 + wm, ng = n0 + wn;
#pragma unroll
    for (int mi = 0; mi < NA; mi++) {
        int r = mg + 16 * mi + (lane >> 2);
#pragma unroll
        for (int nj = 0; nj < 2 * NB; nj++) {
            int cg = ng + 8 * nj + 2 * (lane & 3);
            float b0 = p.bias[cg], b1 = p.bias[cg + 1];
            float v00 = acc[mi][nj][0] + b0, v01 = acc[mi][nj][1] + b1;
            float v10 = acc[mi][nj][2] + b0, v11 = acc[mi][nj][3] + b1;
            if (p.epi == 1) {
                v00 = fmaxf(v00, 0.f); v01 = fmaxf(v01, 0.f);
                v10 = fmaxf(v10, 0.f); v11 = fmaxf(v11, 0.f);
                __nv_bfloat162 h2, l2;
                split2(v00, h2.x, l2.x); split2(v01, h2.y, l2.y);
                *(__nv_bfloat162*)(p.Chi + (long)r * p.ldch + cg) = h2;
                *(__nv_bfloat162*)(p.Clo + (long)r * p.ldch + cg) = l2;
                split2(v10, h2.x, l2.x); split2(v11, h2.y, l2.y);
                *(__nv_bfloat162*)(p.Chi + (long)(r + 8) * p.ldch + cg) = h2;
                *(__nv_bfloat162*)(p.Clo + (long)(r + 8) * p.ldch + cg) = l2;
            } else {
                float2 f2;
                f2.x = v00; f2.y = v01;
                *(float2*)(p.C + (long)r * p.ldc + cg) = f2;
                f2.x = v10; f2.y = v11;
                *(float2*)(p.C + (long)(r + 8) * p.ldc + cg) = f2;
            }
        }
    }
}

// Two instantiations: big (L2 gates) and small (L1/L4/L5)
constexpr int SMEM_BIG   = 2 * 2 * (128 * ROW_B + 64 * ROW_B);  // 61440
constexpr int SMEM_SMALL = 2 * 2 * (64 * ROW_B + 64 * ROW_B);   // 40960

// ---------------- GRU gate combine ----------------
__global__ __launch_bounds__(256) void gru_kernel(float* __restrict__ hout) {
    int idx = blockIdx.x * blockDim.x + threadIdx.x;
    int b = idx >> 9;
    int d = (idx & 511) << 2;
    const float* gi = g_gi + (long)b * G3 + d;
    const float* gh = g_gh + (long)b * G3 + d;
    float4 ir  = *(const float4*)(gi);
    float4 iu  = *(const float4*)(gi + DETn);
    float4 in_ = *(const float4*)(gi + 2 * DETn);
    float4 hr  = *(const float4*)(gh);
    float4 hu  = *(const float4*)(gh + DETn);
    float4 hn  = *(const float4*)(gh + 2 * DETn);
    float4 hp  = *(const float4*)(g_h + (long)b * DETn + d);
    float4 hs;
#define GRUC(X) { \
    float r = 1.f / (1.f + expf(-(ir.X + hr.X))); \
    float u = 1.f / (1.f + expf(-(iu.X + hu.X))); \
    float n = tanhf(in_.X + r * hn.X);            \
    hs.X = (1.f - u) * n + u * hp.X; }
    GRUC(x) GRUC(y) GRUC(z) GRUC(w)
#undef GRUC
    *(float4*)(g_h + (long)b * DETn + d) = hs;
    *(float4*)(hout + (long)b * (Tt * DETn) + d) = hs;
    long o = (long)b * DETn + d;
#pragma unroll
    for (int j = 0; j < 4; j++) {
        float v = (&hs.x)[j];
        split2(v, g_h_hi[o + j], g_h_lo[o + j]);
    }
}

// ---------------- ms-head finalize ----------------
__device__ __forceinline__ float softplusf(float x) {
    return (x > 20.f) ? x : log1pf(expf(x));
}
__global__ __launch_bounds__(256) void combine_kernel(
    const float* __restrict__ eps, float* pm_o, float* ps_o, float* z_o,
    float* qm_o, float* qs_o) {
    int i = blockIdx.x * 256 + threadIdx.x;
    int b = i >> 8, n = i & 255;
    long o = (long)b * (Tt * STOn) + n;
    float m  = g_ms_p[b * 512 + n];
    float ls = g_ms_p[b * 512 + 256 + n];
    float s  = softplusf(ls) + 0.1f;
    float z  = fmaf(s, eps[o], m);
    pm_o[o] = m; ps_o[o] = s; z_o[o] = z;
    split2(z, g_z_hi[b * 256 + n], g_z_lo[b * 256 + n]);
    float qm  = g_ms_q[b * 512 + n];
    float qls = g_ms_q[b * 512 + 256 + n];
    qm_o[o] = qm; qs_o[o] = softplusf(qls) + 0.1f;
}

// ---------------- merged prep: zero + elementwise splits ----------------
struct SplitJob { const float* src; bf16* hi; bf16* lo; long n; };

__global__ __launch_bounds__(256) void prep_split_kernel(
    SplitJob j0, SplitJob j1, SplitJob j2, SplitJob j3) {
    long stride = (long)gridDim.x * blockDim.x;
    long gt = (long)blockIdx.x * blockDim.x + threadIdx.x;
    for (long i = gt; i < Bb * DETn; i += stride) {
        g_h[i] = 0.f;
        g_h_hi[i] = __float2bfloat16(0.f);
        g_h_lo[i] = __float2bfloat16(0.f);
    }
    for (long i = gt; i < Bb * STOn; i += stride) {
        g_z_hi[i] = __float2bfloat16(0.f);
        g_z_lo[i] = __float2bfloat16(0.f);
    }
    SplitJob jobs[4] = {j0, j1, j2, j3};
#pragma unroll
    for (int jj = 0; jj < 4; jj++) {
        SplitJob j = jobs[jj];
        for (long i = gt; i < j.n; i += stride)
            split2(j.src[i], j.hi[i], j.lo[i]);
    }
}

// ---------------- merged prep: transposed splits ----------------
struct TJob { const float* src; bf16* hi; bf16* lo; int R, C, tileEnd; };

__global__ __launch_bounds__(256) void prep_tsplit_kernel(
    TJob a, TJob b, TJob c, TJob d, TJob e) {
    __shared__ float t[32][33];
    int bid = blockIdx.x;
    TJob j; int tileBase;
    if      (bid < a.tileEnd) { j = a; tileBase = 0; }
    else if (bid < b.tileEnd) { j = b; tileBase = a.tileEnd; }
    else if (bid < c.tileEnd) { j = c; tileBase = b.tileEnd; }
    else if (bid < d.tileEnd) { j = d; tileBase = c.tileEnd; }
    else                      { j = e; tileBase = d.tileEnd; }
    int tile = bid - tileBase;
    int tiles_x = j.C / 32;
    int c0 = (tile % tiles_x) * 32;
    int r0 = (tile / tiles_x) * 32;
    int tx = threadIdx.x & 31, ty = threadIdx.x >> 5;   // 32 x 8
    for (int i = ty; i < 32; i += 8)
        t[i][tx] = j.src[(long)(r0 + i) * j.C + c0 + tx];
    __syncthreads();
    for (int i = ty; i < 32; i += 8) {
        float v = t[tx][i];
        long o = (long)(c0 + i) * j.R + r0 + tx;
        split2(v, j.hi[o], j.lo[o]);
    }
}

// ---------------- host orchestration ----------------
static void* sym(const void* s) { void* p; cudaGetSymbolAddress(&p, s); return p; }

extern "C" void kernel_launch(void* const* d_in, const int* in_sizes, int n_in,
                              void* d_out, int out_size) {
    const float* obs        = (const float*)d_in[0];
    const float* actions    = (const float*)d_in[1];
    const float* noise      = (const float*)d_in[4];
    const float* W_rnn      = (const float*)d_in[5];
    const float* b_rnn      = (const float*)d_in[6];
    const float* Wih        = (const float*)d_in[7];
    const float* Whh        = (const float*)d_in[8];
    const float* bih        = (const float*)d_in[9];
    const float* bhh        = (const float*)d_in[10];
    const float* W_post_in  = (const float*)d_in[11];
    const float* b_post_in  = (const float*)d_in[12];
    const float* W_post_ms  = (const float*)d_in[13];
    const float* b_post_ms  = (const float*)d_in[14];
    const float* W_prior_in = (const float*)d_in[15];
    const float* b_prior_in = (const float*)d_in[16];
    const float* W_prior_ms = (const float*)d_in[17];
    const float* b_prior_ms = (const float*)d_in[18];
    float* out = (float*)d_out;

    cudaFuncSetAttribute(tgemm_kernel<128, 64, 4, 2>,
                         cudaFuncAttributeMaxDynamicSharedMemorySize, SMEM_BIG);
    cudaFuncSetAttribute(tgemm_kernel<64, 64, 2, 4>,
                         cudaFuncAttributeMaxDynamicSharedMemorySize, SMEM_SMALL);

    bf16 *Bhh_hi = (bf16*)sym(g_Bhh_hi), *Bhh_lo = (bf16*)sym(g_Bhh_lo);
    bf16 *Bih_hi = (bf16*)sym(g_Bih_hi), *Bih_lo = (bf16*)sym(g_Bih_lo);
    bf16 *Brnn_hi = (bf16*)sym(g_Brnn_hi), *Brnn_lo = (bf16*)sym(g_Brnn_lo);
    bf16 *Bpo_hi = (bf16*)sym(g_Bpo_hi), *Bpo_lo = (bf16*)sym(g_Bpo_lo);
    bf16 *Bpr_hi = (bf16*)sym(g_Bpr_hi), *Bpr_lo = (bf16*)sym(g_Bpr_lo);
    bf16 *Bpm_hi = (bf16*)sym(g_Bpm_hi), *Bpm_lo = (bf16*)sym(g_Bpm_lo);
    bf16 *Bqm_hi = (bf16*)sym(g_Bqm_hi), *Bqm_lo = (bf16*)sym(g_Bqm_lo);
    bf16 *obs_hi = (bf16*)sym(g_obs_hi), *obs_lo = (bf16*)sym(g_obs_lo);
    bf16 *act_hi = (bf16*)sym(g_act_hi), *act_lo = (bf16*)sym(g_act_lo);
    bf16 *zact   = (bf16*)sym(g_zact);
    bf16 *h_hi = (bf16*)sym(g_h_hi), *h_lo = (bf16*)sym(g_h_lo);
    bf16 *z_hi = (bf16*)sym(g_z_hi), *z_lo = (bf16*)sym(g_z_lo);
    bf16 *rn_hi = (bf16*)sym(g_rn_hi), *rn_lo = (bf16*)sym(g_rn_lo);
    bf16 *pf_hi = (bf16*)sym(g_pf_hi), *pf_lo = (bf16*)sym(g_pf_lo);
    bf16 *rf_hi = (bf16*)sym(g_rf_hi), *rf_lo = (bf16*)sym(g_rf_lo);
    float *gi_p = (float*)sym(g_gi), *gh_p = (float*)sym(g_gh);
    float *msp = (float*)sym(g_ms_p), *msq = (float*)sym(g_ms_q);

    float* out_h  = out;
    float* out_z  = out_h  + (long)Bb * Tt * DETn;
    float* out_pm = out_z  + (long)Bb * Tt * STOn;
    float* out_ps = out_pm + (long)Bb * Tt * STOn;
    float* out_qm = out_ps + (long)Bb * Tt * STOn;
    float* out_qs = out_qm + (long)Bb * Tt * STOn;

    // ---- prep (2 launches): zero+splits, then transposed splits ----
    {
        SplitJob s0 = {Whh,     Bhh_hi, Bhh_lo, (long)G3 * DETn};
        SplitJob s1 = {Wih,     Bih_hi, Bih_lo, (long)G3 * HIDn};
        SplitJob s2 = {obs,     obs_hi, obs_lo, (long)Bb * Tt * Ee};
        SplitJob s3 = {actions, act_hi, act_lo, (long)Bb * Tt * Aa};
        prep_split_kernel<<<2048, 256>>>(s0, s1, s2, s3);

        int t0 = (320 / 32) * (HIDn / 32);             // 320
        int t1 = t0 + (3072 / 32) * (HIDn / 32);       // +3072
        int t2 = t1 + (DETn / 32) * (HIDn / 32);       // +2048
        int t3 = t2 + (HIDn / 32) * (512 / 32);        // +512
        int t4 = t3 + (HIDn / 32) * (512 / 32);        // +512
        TJob a = {W_rnn,      Brnn_hi, Brnn_lo, 320,  HIDn, t0};
        TJob b = {W_post_in,  Bpo_hi,  Bpo_lo,  3072, HIDn, t1};
        TJob c = {W_prior_in, Bpr_hi,  Bpr_lo,  DETn, HIDn, t2};
        TJob d = {W_post_ms,  Bpm_hi,  Bpm_lo,  HIDn, 512,  t3};
        TJob e = {W_prior_ms, Bqm_hi,  Bqm_lo,  HIDn, 512,  t4};
        prep_tsplit_kernel<<<t4, 256>>>(a, b, c, d, e);
    }

    for (int t = 0; t < Tt; t++) {
        // L1: rnn_in = relu([z_prev | a_prev] @ W_rnn + b) -> rn hi/lo   (64 CTAs)
        TG prnn = {};
        prnn.A1hi = z_hi; prnn.A1lo = z_lo; prnn.lda1 = STOn; prnn.K1 = STOn;
        if (t > 0) { prnn.A2hi = act_hi + (long)(t - 1) * Aa; prnn.A2lo = act_lo + (long)(t - 1) * Aa; prnn.lda2 = (long)Tt * Aa; }
        else       { prnn.A2hi = zact; prnn.A2lo = zact; prnn.lda2 = Aa; }
        prnn.Bhi = Brnn_hi; prnn.Blo = Brnn_lo; prnn.ldb = 320;
        prnn.bias = b_rnn; prnn.K = 320; prnn.Ntiles = HIDn / 64;
        prnn.epi = 1; prnn.Chi = rn_hi; prnn.Clo = rn_lo; prnn.ldch = HIDn;
        tgemm_kernel<64, 64, 2, 4><<<dim3(4, HIDn / 64, 1), 256, SMEM_SMALL>>>(prnn, prnn);

        // L2: z0: gh = h @ Whh^T + bhh ; z1: gi = rnn @ Wih^T + bih  (384 CTAs, BM=128)
        TG pgh = {};
        pgh.A1hi = h_hi; pgh.A1lo = h_lo; pgh.lda1 = DETn; pgh.K1 = DETn;
        pgh.Bhi = Bhh_hi; pgh.Blo = Bhh_lo; pgh.ldb = DETn;
        pgh.bias = bhh; pgh.K = DETn; pgh.Ntiles = G3 / 64;
        pgh.epi = 0; pgh.C = gh_p; pgh.ldc = G3;
        TG pgi = {};
        pgi.A1hi = rn_hi; pgi.A1lo = rn_lo; pgi.lda1 = HIDn; pgi.K1 = HIDn;
        pgi.Bhi = Bih_hi; pgi.Blo = Bih_lo; pgi.ldb = HIDn;
        pgi.bias = bih; pgi.K = HIDn; pgi.Ntiles = G3 / 64;
        pgi.epi = 0; pgi.C = gi_p; pgi.ldc = G3;
        tgemm_kernel<128, 64, 4, 2><<<dim3(2, G3 / 64, 2), 256, SMEM_BIG>>>(pgh, pgi);

        // L3: GRU elementwise -> h
        gru_kernel<<<(Bb * DETn / 4) / 256, 256>>>(out_h + (long)t * DETn);

        // L4: z0: pf = relu([h|obs] @ Wpost_in + b) ; z1: rf = relu(h @ Wprior_in + b)  (128 CTAs)
        TG ppo = {};
        ppo.A1hi = h_hi; ppo.A1lo = h_lo; ppo.lda1 = DETn; ppo.K1 = DETn;
        ppo.A2hi = obs_hi + (long)t * Ee; ppo.A2lo = obs_lo + (long)t * Ee; ppo.lda2 = (long)Tt * Ee;
        ppo.Bhi = Bpo_hi; ppo.Blo = Bpo_lo; ppo.ldb = 3072;
        ppo.bias = b_post_in; ppo.K = 3072; ppo.Ntiles = HIDn / 64;
        ppo.epi = 1; ppo.Chi = pf_hi; ppo.Clo = pf_lo; ppo.ldch = HIDn;
        TG ppr = {};
        ppr.A1hi = h_hi; ppr.A1lo = h_lo; ppr.lda1 = DETn; ppr.K1 = DETn;
        ppr.Bhi = Bpr_hi; ppr.Blo = Bpr_lo; ppr.ldb = DETn;
        ppr.bias = b_prior_in; ppr.K = DETn; ppr.Ntiles = HIDn / 64;
        ppr.epi = 1; ppr.Chi = rf_hi; ppr.Clo = rf_lo; ppr.ldch = HIDn;
        tgemm_kernel<64, 64, 2, 4><<<dim3(4, HIDn / 64, 2), 256, SMEM_SMALL>>>(ppo, ppr);

        // L5: z0: ms_post = pf @ Wpm^T + b ; z1: ms_prior = rf @ Wqm^T + b  (64 CTAs)
        TG qpm = {};
        qpm.A1hi = pf_hi; qpm.A1lo = pf_lo; qpm.lda1 = HIDn; qpm.K1 = HIDn;
        qpm.Bhi = Bpm_hi; qpm.Blo = Bpm_lo; qpm.ldb = HIDn;
        qpm.bias = b_post_ms; qpm.K = HIDn; qpm.Ntiles = 512 / 64;
        qpm.epi = 0; qpm.C = msp; qpm.ldc = 512;
        TG qqm = {};
        qqm.A1hi = rf_hi; qqm.A1lo = rf_lo; qqm.lda1 = HIDn; qqm.K1 = HIDn;
        qqm.Bhi = Bqm_hi; qqm.Blo = Bqm_lo; qqm.ldb = HIDn;
        qqm.bias = b_prior_ms; qqm.K = HIDn; qqm.Ntiles = 512 / 64;
        qqm.epi = 0; qqm.C = msq; qqm.ldc = 512;
        tgemm_kernel<64, 64, 2, 4><<<dim3(4, 512 / 64, 2), 256, SMEM_SMALL>>>(qpm, qqm);

        // L6: finalize heads, rsample z, split z to bf16
        combine_kernel<<<256, 256>>>(noise + (long)t * STOn,
                                     out_pm + (long)t * STOn, out_ps + (long)t * STOn,
                                     out_z + (long)t * STOn,
                                     out_qm + (long)t * STOn, out_qs + (long)t * STOn);
    }
}

// round 6
// speedup vs baseline: 4.5304x; 1.0202x over previous
#include <cuda_runtime.h>
#include <cuda_bf16.h>
#include <math.h>
#include <stdint.h>

// ---------------- problem constants ----------------
constexpr int Bb  = 256;
constexpr int Tt  = 64;
constexpr int Aa  = 64;
constexpr int Ee  = 1024;
constexpr int HIDn = 1024;
constexpr int DETn = 2048;
constexpr int STOn = 256;
constexpr int G3  = 3 * DETn;   // 6144

typedef __nv_bfloat16 bf16;

// ---------------- device-global scratch (no allocation allowed) ----------------
__device__ __align__(256) bf16 g_Bhh_hi [G3 * DETn],  g_Bhh_lo [G3 * DETn];
__device__ __align__(256) bf16 g_Bih_hi [G3 * HIDn],  g_Bih_lo [G3 * HIDn];
__device__ __align__(256) bf16 g_Brnn_hi[HIDn * 320], g_Brnn_lo[HIDn * 320];
__device__ __align__(256) bf16 g_Bpo_hi [HIDn * 3072],g_Bpo_lo [HIDn * 3072];
__device__ __align__(256) bf16 g_Bpr_hi [HIDn * DETn],g_Bpr_lo [HIDn * DETn];
__device__ __align__(256) bf16 g_Bpm_hi [512 * HIDn], g_Bpm_lo [512 * HIDn];   // interleaved rows
__device__ __align__(256) bf16 g_Bqm_hi [512 * HIDn], g_Bqm_lo [512 * HIDn];   // interleaved rows
__device__ __align__(256) float g_bpm_int[512], g_bqm_int[512];
__device__ __align__(256) bf16 g_obs_hi[Bb * Tt * Ee], g_obs_lo[Bb * Tt * Ee];
__device__ __align__(256) bf16 g_act_hi[Bb * Tt * Aa], g_act_lo[Bb * Tt * Aa];
__device__ __align__(256) bf16 g_zact  [Bb * Aa];      // stays zero
__device__ __align__(256) float g_h   [Bb * DETn];
__device__ __align__(256) bf16  g_h_hi[Bb * DETn], g_h_lo[Bb * DETn];
__device__ __align__(256) bf16  g_z_hi[Bb * STOn], g_z_lo[Bb * STOn];
__device__ __align__(256) bf16  g_rn_hi[Bb * HIDn], g_rn_lo[Bb * HIDn];
__device__ __align__(256) bf16  g_pf_hi[Bb * HIDn], g_pf_lo[Bb * HIDn];
__device__ __align__(256) bf16  g_rf_hi[Bb * HIDn], g_rf_lo[Bb * HIDn];
__device__ __align__(256) float g_gi[Bb * G3], g_gh[Bb * G3];

// ---------------- helpers ----------------
__device__ __forceinline__ uint32_t smem_u32(const void* p) {
    uint32_t a;
    asm("{ .reg .u64 t; cvta.to.shared.u64 t, %1; cvt.u32.u64 %0, t; }" : "=r"(a) : "l"(p));
    return a;
}
__device__ __forceinline__ void cpa16(uint32_t dst, const void* src) {
    asm volatile("cp.async.cg.shared.global [%0], [%1], 16;" :: "r"(dst), "l"(src) : "memory");
}
__device__ __forceinline__ void ldsm4(uint32_t& r0, uint32_t& r1, uint32_t& r2, uint32_t& r3,
                                      uint32_t a) {
    asm volatile("ldmatrix.sync.aligned.m8n8.x4.shared.b16 {%0,%1,%2,%3}, [%4];"
                 : "=r"(r0), "=r"(r1), "=r"(r2), "=r"(r3) : "r"(a));
}
__device__ __forceinline__ void mmabf(float* c, const uint32_t* a, const uint32_t* b) {
    asm volatile(
        "mma.sync.aligned.m16n8k16.row.col.f32.bf16.bf16.f32 "
        "{%0,%1,%2,%3}, {%4,%5,%6,%7}, {%8,%9}, {%0,%1,%2,%3};"
        : "+f"(c[0]), "+f"(c[1]), "+f"(c[2]), "+f"(c[3])
        : "r"(a[0]), "r"(a[1]), "r"(a[2]), "r"(a[3]), "r"(b[0]), "r"(b[1]));
}
__device__ __forceinline__ void split2(float v, bf16& h, bf16& l) {
    h = __float2bfloat16(v);
    l = __float2bfloat16(v - __bfloat162float(h));
}
__device__ __forceinline__ float softplusf(float x) {
    return (x > 20.f) ? x : log1pf(expf(x));
}

// ---------------- tensor GEMM: C[256,N] = epi([A1|A2] @ B^T + bias), 3-term bf16 split ----
// epi 0: fp32 + bias; epi 1: relu + bf16 hi/lo split; epi 2: fused ms-head (interleaved
//        mean/std columns -> softplus, rsample, z split).
struct TG {
    const bf16 *A1hi, *A1lo, *A2hi, *A2lo;
    const bf16 *Bhi, *Blo;
    const float* bias;
    float* C;            // epi 0
    bf16 *Chi, *Clo;     // epi 1
    float *o_m, *o_s, *o_z;   // epi 2
    const float* eps;         // epi 2 (posterior)
    bf16 *zhi, *zlo;          // epi 2 (posterior)
    long lda1, lda2, ldb, ldo;
    int K1, K, Ntiles, ldc, ldch, epi;
};

constexpr int ROW_B = 80;     // padded smem row (bytes) for 32 bf16
constexpr int NSTAGE = 3;

template<int BM, int BN, int WRM, int WRN>
__global__ __launch_bounds__(256, 2) void tgemm_kernel(TG p0, TG p1) {
    constexpr int NA = (BM / WRM) / 16;
    constexpr int NB = (BN / WRN) / 16;
    constexpr int A_PART = BM * ROW_B;
    constexpr int B_PART = BN * ROW_B;
    constexpr int STAGE  = 2 * (A_PART + B_PART);

    TG p = blockIdx.z ? p1 : p0;
    if ((int)blockIdx.y >= p.Ntiles) return;

    extern __shared__ char smem[];
    const uint32_t sb = smem_u32(smem);
    const int tid = threadIdx.x, wid = tid >> 5, lane = tid & 31;
    const int m0 = blockIdx.x * BM, n0 = blockIdx.y * BN;
    const int wm = (wid % WRM) * (BM / WRM), wn = (wid / WRM) * (BN / WRN);

    auto loadChunk = [&](int c) {
        uint32_t stg = sb + (c % NSTAGE) * STAGE;
        long koff = (long)c * 32;
        const bf16 *ah, *al; long lda;
        if (koff < p.K1) { ah = p.A1hi; al = p.A1lo; lda = p.lda1; }
        else             { ah = p.A2hi; al = p.A2lo; lda = p.lda2; koff -= p.K1; }
        const bf16* a_hi = ah + (long)m0 * lda + koff;
        const bf16* a_lo = al + (long)m0 * lda + koff;
        const bf16* b_hi = p.Bhi + (long)n0 * p.ldb + (long)c * 32;
        const bf16* b_lo = p.Blo + (long)n0 * p.ldb + (long)c * 32;
#pragma unroll
        for (int o = tid; o < (BM + BN) * 4; o += 256) {
            int row = o >> 2, seg = o & 3;
            if (row < BM) {
                cpa16(stg + row * ROW_B + seg * 16,          a_hi + (long)row * lda + seg * 8);
                cpa16(stg + A_PART + row * ROW_B + seg * 16, a_lo + (long)row * lda + seg * 8);
            } else {
                int br = row - BM;
                cpa16(stg + 2 * A_PART + br * ROW_B + seg * 16,
                      b_hi + (long)br * p.ldb + seg * 8);
                cpa16(stg + 2 * A_PART + B_PART + br * ROW_B + seg * 16,
                      b_lo + (long)br * p.ldb + seg * 8);
            }
        }
        asm volatile("cp.async.commit_group;" ::: "memory");
    };

    float acc[NA][2 * NB][4];
#pragma unroll
    for (int i = 0; i < NA; i++)
#pragma unroll
        for (int j = 0; j < 2 * NB; j++)
#pragma unroll
            for (int k = 0; k < 4; k++) acc[i][j][k] = 0.f;

    const int nch = p.K >> 5;
    loadChunk(0);
    loadChunk(1);
    for (int c = 0; c < nch; c++) {
        asm volatile("cp.async.wait_group 1;" ::: "memory");   // chunk c resident
        __syncthreads();                                       // all warps done with c-1
        if (c + 2 < nch) loadChunk(c + 2);                     // overwrites stage of c-1: safe

        const uint32_t stg = sb + (c % NSTAGE) * STAGE;
#pragma unroll
        for (int kk = 0; kk < 2; kk++) {
            uint32_t Ah[NA][4], Al[NA][4], Bh[NB][4], Bl[NB][4];
#pragma unroll
            for (int mi = 0; mi < NA; mi++) {
                int row = wm + 16 * mi + (lane & 15);
                uint32_t ad = stg + row * ROW_B + kk * 32 + ((lane >> 4) << 4);
                ldsm4(Ah[mi][0], Ah[mi][1], Ah[mi][2], Ah[mi][3], ad);
                ldsm4(Al[mi][0], Al[mi][1], Al[mi][2], Al[mi][3], ad + A_PART);
            }
#pragma unroll
            for (int pp = 0; pp < NB; pp++) {
                int row = wn + 16 * pp + ((lane >> 4) << 3) + (lane & 7);
                uint32_t bd = stg + 2 * A_PART + row * ROW_B + kk * 32 + (((lane >> 3) & 1) << 4);
                ldsm4(Bh[pp][0], Bh[pp][1], Bh[pp][2], Bh[pp][3], bd);
                ldsm4(Bl[pp][0], Bl[pp][1], Bl[pp][2], Bl[pp][3], bd + B_PART);
            }
#pragma unroll
            for (int mi = 0; mi < NA; mi++)
#pragma unroll
                for (int pp = 0; pp < NB; pp++)
#pragma unroll
                    for (int tt = 0; tt < 2; tt++) {
                        float* ca = acc[mi][2 * pp + tt];
                        mmabf(ca, Ah[mi], &Bh[pp][2 * tt]);
                        mmabf(ca, Ah[mi], &Bl[pp][2 * tt]);
                        mmabf(ca, Al[mi], &Bh[pp][2 * tt]);
                    }
        }
    }

    // ---- epilogue ----
    const int mg = m0 + wm, ng = n0 + wn;
#pragma unroll
    for (int mi = 0; mi < NA; mi++) {
        int r = mg + 16 * mi + (lane >> 2);
#pragma unroll
        for (int nj = 0; nj < 2 * NB; nj++) {
            int cg = ng + 8 * nj + 2 * (lane & 3);
            float b0 = p.bias[cg], b1 = p.bias[cg + 1];
            float v00 = acc[mi][nj][0] + b0, v01 = acc[mi][nj][1] + b1;
            float v10 = acc[mi][nj][2] + b0, v11 = acc[mi][nj][3] + b1;
            if (p.epi == 1) {
                v00 = fmaxf(v00, 0.f); v01 = fmaxf(v01, 0.f);
                v10 = fmaxf(v10, 0.f); v11 = fmaxf(v11, 0.f);
                __nv_bfloat162 h2, l2;
                split2(v00, h2.x, l2.x); split2(v01, h2.y, l2.y);
                *(__nv_bfloat162*)(p.Chi + (long)r * p.ldch + cg) = h2;
                *(__nv_bfloat162*)(p.Clo + (long)r * p.ldch + cg) = l2;
                split2(v10, h2.x, l2.x); split2(v11, h2.y, l2.y);
                *(__nv_bfloat162*)(p.Chi + (long)(r + 8) * p.ldch + cg) = h2;
                *(__nv_bfloat162*)(p.Clo + (long)(r + 8) * p.ldch + cg) = l2;
            } else if (p.epi == 0) {
                float2 f2;
                f2.x = v00; f2.y = v01;
                *(float2*)(p.C + (long)r * p.ldc + cg) = f2;
                f2.x = v10; f2.y = v11;
                *(float2*)(p.C + (long)(r + 8) * p.ldc + cg) = f2;
            } else {
                // epi 2: interleaved (mean, std) pair per thread
                int j = cg >> 1;
#pragma unroll
                for (int hh = 0; hh < 2; hh++) {
                    int rr = r + 8 * hh;
                    float mean = hh ? v10 : v00;
                    float sraw = hh ? v11 : v01;
                    float s = softplusf(sraw) + 0.1f;
                    long o = (long)rr * p.ldo + j;
                    p.o_m[o] = mean;
                    p.o_s[o] = s;
                    if (p.o_z) {
                        float zv = fmaf(s, p.eps[o], mean);
                        p.o_z[o] = zv;
                        split2(zv, p.zhi[rr * STOn + j], p.zlo[rr * STOn + j]);
                    }
                }
            }
        }
    }
}

constexpr int SMEM_BIG   = NSTAGE * 2 * (128 * ROW_B + 64 * ROW_B);  // 92160
constexpr int SMEM_SMALL = NSTAGE * 2 * (64 * ROW_B + 64 * ROW_B);   // 61440

// ---------------- GRU gate combine ----------------
__global__ __launch_bounds__(256) void gru_kernel(float* __restrict__ hout) {
    int idx = blockIdx.x * blockDim.x + threadIdx.x;
    int b = idx >> 9;
    int d = (idx & 511) << 2;
    const float* gi = g_gi + (long)b * G3 + d;
    const float* gh = g_gh + (long)b * G3 + d;
    float4 ir  = *(const float4*)(gi);
    float4 iu  = *(const float4*)(gi + DETn);
    float4 in_ = *(const float4*)(gi + 2 * DETn);
    float4 hr  = *(const float4*)(gh);
    float4 hu  = *(const float4*)(gh + DETn);
    float4 hn  = *(const float4*)(gh + 2 * DETn);
    float4 hp  = *(const float4*)(g_h + (long)b * DETn + d);
    float4 hs;
#define GRUC(X) { \
    float r = 1.f / (1.f + expf(-(ir.X + hr.X))); \
    float u = 1.f / (1.f + expf(-(iu.X + hu.X))); \
    float n = tanhf(in_.X + r * hn.X);            \
    hs.X = (1.f - u) * n + u * hp.X; }
    GRUC(x) GRUC(y) GRUC(z) GRUC(w)
#undef GRUC
    *(float4*)(g_h + (long)b * DETn + d) = hs;
    *(float4*)(hout + (long)b * (Tt * DETn) + d) = hs;
    long o = (long)b * DETn + d;
#pragma unroll
    for (int j = 0; j < 4; j++) {
        float v = (&hs.x)[j];
        split2(v, g_h_hi[o + j], g_h_lo[o + j]);
    }
}

// ---------------- merged prep: zero + elementwise splits + bias interleave ----------------
struct SplitJob { const float* src; bf16* hi; bf16* lo; long n; };

__global__ __launch_bounds__(256) void prep_split_kernel(
    SplitJob j0, SplitJob j1, SplitJob j2, SplitJob j3,
    const float* bpm, const float* bqm) {
    long stride = (long)gridDim.x * blockDim.x;
    long gt = (long)blockIdx.x * blockDim.x + threadIdx.x;
    for (long i = gt; i < Bb * DETn; i += stride) {
        g_h[i] = 0.f;
        g_h_hi[i] = __float2bfloat16(0.f);
        g_h_lo[i] = __float2bfloat16(0.f);
    }
    for (long i = gt; i < Bb * STOn; i += stride) {
        g_z_hi[i] = __float2bfloat16(0.f);
        g_z_lo[i] = __float2bfloat16(0.f);
    }
    for (long i = gt; i < 512; i += stride) {
        int c = (int)(i >> 1) + ((int)i & 1) * 256;
        g_bpm_int[i] = bpm[c];
        g_bqm_int[i] = bqm[c];
    }
    SplitJob jobs[4] = {j0, j1, j2, j3};
#pragma unroll
    for (int jj = 0; jj < 4; jj++) {
        SplitJob j = jobs[jj];
        for (long i = gt; i < j.n; i += stride)
            split2(j.src[i], j.hi[i], j.lo[i]);
    }
}

// ---------------- merged prep: transposed splits (optionally column-interleaved) --------
struct TJob { const float* src; bf16* hi; bf16* lo; int R, C, tileEnd, ilv; };

__global__ __launch_bounds__(256) void prep_tsplit_kernel(
    TJob a, TJob b, TJob c, TJob d, TJob e) {
    __shared__ float t[32][33];
    int bid = blockIdx.x;
    TJob j; int tileBase;
    if      (bid < a.tileEnd) { j = a; tileBase = 0; }
    else if (bid < b.tileEnd) { j = b; tileBase = a.tileEnd; }
    else if (bid < c.tileEnd) { j = c; tileBase = b.tileEnd; }
    else if (bid < d.tileEnd) { j = d; tileBase = c.tileEnd; }
    else                      { j = e; tileBase = d.tileEnd; }
    int tile = bid - tileBase;
    int tiles_x = j.C / 32;
    int c0 = (tile % tiles_x) * 32;
    int r0 = (tile / tiles_x) * 32;
    int tx = threadIdx.x & 31, ty = threadIdx.x >> 5;
    for (int i = ty; i < 32; i += 8)
        t[i][tx] = j.src[(long)(r0 + i) * j.C + c0 + tx];
    __syncthreads();
    for (int i = ty; i < 32; i += 8) {
        float v = t[tx][i];
        int cidx = c0 + i;
        int drow = j.ilv ? ((cidx < 256) ? 2 * cidx : 2 * (cidx - 256) + 1) : cidx;
        long o = (long)drow * j.R + r0 + tx;
        split2(v, j.hi[o], j.lo[o]);
    }
}

// ---------------- host orchestration ----------------
static void* sym(const void* s) { void* p; cudaGetSymbolAddress(&p, s); return p; }

extern "C" void kernel_launch(void* const* d_in, const int* in_sizes, int n_in,
                              void* d_out, int out_size) {
    const float* obs        = (const float*)d_in[0];
    const float* actions    = (const float*)d_in[1];
    const float* noise      = (const float*)d_in[4];
    const float* W_rnn      = (const float*)d_in[5];
    const float* b_rnn      = (const float*)d_in[6];
    const float* Wih        = (const float*)d_in[7];
    const float* Whh        = (const float*)d_in[8];
    const float* bih        = (const float*)d_in[9];
    const float* bhh        = (const float*)d_in[10];
    const float* W_post_in  = (const float*)d_in[11];
    const float* b_post_in  = (const float*)d_in[12];
    const float* W_post_ms  = (const float*)d_in[13];
    const float* b_post_ms  = (const float*)d_in[14];
    const float* W_prior_in = (const float*)d_in[15];
    const float* b_prior_in = (const float*)d_in[16];
    const float* W_prior_ms = (const float*)d_in[17];
    const float* b_prior_ms = (const float*)d_in[18];
    float* out = (float*)d_out;

    cudaFuncSetAttribute(tgemm_kernel<128, 64, 4, 2>,
                         cudaFuncAttributeMaxDynamicSharedMemorySize, SMEM_BIG);
    cudaFuncSetAttribute(tgemm_kernel<64, 64, 2, 4>,
                         cudaFuncAttributeMaxDynamicSharedMemorySize, SMEM_SMALL);

    bf16 *Bhh_hi = (bf16*)sym(g_Bhh_hi), *Bhh_lo = (bf16*)sym(g_Bhh_lo);
    bf16 *Bih_hi = (bf16*)sym(g_Bih_hi), *Bih_lo = (bf16*)sym(g_Bih_lo);
    bf16 *Brnn_hi = (bf16*)sym(g_Brnn_hi), *Brnn_lo = (bf16*)sym(g_Brnn_lo);
    bf16 *Bpo_hi = (bf16*)sym(g_Bpo_hi), *Bpo_lo = (bf16*)sym(g_Bpo_lo);
    bf16 *Bpr_hi = (bf16*)sym(g_Bpr_hi), *Bpr_lo = (bf16*)sym(g_Bpr_lo);
    bf16 *Bpm_hi = (bf16*)sym(g_Bpm_hi), *Bpm_lo = (bf16*)sym(g_Bpm_lo);
    bf16 *Bqm_hi = (bf16*)sym(g_Bqm_hi), *Bqm_lo = (bf16*)sym(g_Bqm_lo);
    float *bpm_i = (float*)sym(g_bpm_int), *bqm_i = (float*)sym(g_bqm_int);
    bf16 *obs_hi = (bf16*)sym(g_obs_hi), *obs_lo = (bf16*)sym(g_obs_lo);
    bf16 *act_hi = (bf16*)sym(g_act_hi), *act_lo = (bf16*)sym(g_act_lo);
    bf16 *zact   = (bf16*)sym(g_zact);
    bf16 *h_hi = (bf16*)sym(g_h_hi), *h_lo = (bf16*)sym(g_h_lo);
    bf16 *z_hi = (bf16*)sym(g_z_hi), *z_lo = (bf16*)sym(g_z_lo);
    bf16 *rn_hi = (bf16*)sym(g_rn_hi), *rn_lo = (bf16*)sym(g_rn_lo);
    bf16 *pf_hi = (bf16*)sym(g_pf_hi), *pf_lo = (bf16*)sym(g_pf_lo);
    bf16 *rf_hi = (bf16*)sym(g_rf_hi), *rf_lo = (bf16*)sym(g_rf_lo);
    float *gi_p = (float*)sym(g_gi), *gh_p = (float*)sym(g_gh);

    float* out_h  = out;
    float* out_z  = out_h  + (long)Bb * Tt * DETn;
    float* out_pm = out_z  + (long)Bb * Tt * STOn;
    float* out_ps = out_pm + (long)Bb * Tt * STOn;
    float* out_qm = out_ps + (long)Bb * Tt * STOn;
    float* out_qs = out_qm + (long)Bb * Tt * STOn;

    // ---- prep (2 launches) ----
    {
        SplitJob s0 = {Whh,     Bhh_hi, Bhh_lo, (long)G3 * DETn};
        SplitJob s1 = {Wih,     Bih_hi, Bih_lo, (long)G3 * HIDn};
        SplitJob s2 = {obs,     obs_hi, obs_lo, (long)Bb * Tt * Ee};
        SplitJob s3 = {actions, act_hi, act_lo, (long)Bb * Tt * Aa};
        prep_split_kernel<<<2048, 256>>>(s0, s1, s2, s3, b_post_ms, b_prior_ms);

        int t0 = (320 / 32) * (HIDn / 32);
        int t1 = t0 + (3072 / 32) * (HIDn / 32);
        int t2 = t1 + (DETn / 32) * (HIDn / 32);
        int t3 = t2 + (HIDn / 32) * (512 / 32);
        int t4 = t3 + (HIDn / 32) * (512 / 32);
        TJob a = {W_rnn,      Brnn_hi, Brnn_lo, 320,  HIDn, t0, 0};
        TJob b = {W_post_in,  Bpo_hi,  Bpo_lo,  3072, HIDn, t1, 0};
        TJob c = {W_prior_in, Bpr_hi,  Bpr_lo,  DETn, HIDn, t2, 0};
        TJob d = {W_post_ms,  Bpm_hi,  Bpm_lo,  HIDn, 512,  t3, 1};
        TJob e = {W_prior_ms, Bqm_hi,  Bqm_lo,  HIDn, 512,  t4, 1};
        prep_tsplit_kernel<<<t4, 256>>>(a, b, c, d, e);
    }

    for (int t = 0; t < Tt; t++) {
        // L1: rnn_in = relu([z_prev | a_prev] @ W_rnn + b) -> rn hi/lo
        TG prnn = {};
        prnn.A1hi = z_hi; prnn.A1lo = z_lo; prnn.lda1 = STOn; prnn.K1 = STOn;
        if (t > 0) { prnn.A2hi = act_hi + (long)(t - 1) * Aa; prnn.A2lo = act_lo + (long)(t - 1) * Aa; prnn.lda2 = (long)Tt * Aa; }
        else       { prnn.A2hi = zact; prnn.A2lo = zact; prnn.lda2 = Aa; }
        prnn.Bhi = Brnn_hi; prnn.Blo = Brnn_lo; prnn.ldb = 320;
        prnn.bias = b_rnn; prnn.K = 320; prnn.Ntiles = HIDn / 64;
        prnn.epi = 1; prnn.Chi = rn_hi; prnn.Clo = rn_lo; prnn.ldch = HIDn;
        tgemm_kernel<64, 64, 2, 4><<<dim3(4, HIDn / 64, 1), 256, SMEM_SMALL>>>(prnn, prnn);

        // L2: z0: gh = h @ Whh^T + bhh ; z1: gi = rnn @ Wih^T + bih
        TG pgh = {};
        pgh.A1hi = h_hi; pgh.A1lo = h_lo; pgh.lda1 = DETn; pgh.K1 = DETn;
        pgh.Bhi = Bhh_hi; pgh.Blo = Bhh_lo; pgh.ldb = DETn;
        pgh.bias = bhh; pgh.K = DETn; pgh.Ntiles = G3 / 64;
        pgh.epi = 0; pgh.C = gh_p; pgh.ldc = G3;
        TG pgi = {};
        pgi.A1hi = rn_hi; pgi.A1lo = rn_lo; pgi.lda1 = HIDn; pgi.K1 = HIDn;
        pgi.Bhi = Bih_hi; pgi.Blo = Bih_lo; pgi.ldb = HIDn;
        pgi.bias = bih; pgi.K = HIDn; pgi.Ntiles = G3 / 64;
        pgi.epi = 0; pgi.C = gi_p; pgi.ldc = G3;
        tgemm_kernel<128, 64, 4, 2><<<dim3(2, G3 / 64, 2), 256, SMEM_BIG>>>(pgh, pgi);

        // L3: GRU elementwise -> h
        gru_kernel<<<(Bb * DETn / 4) / 256, 256>>>(out_h + (long)t * DETn);

        // L4: z0: pf = relu([h|obs] @ Wpost_in + b) ; z1: rf = relu(h @ Wprior_in + b)
        TG ppo = {};
        ppo.A1hi = h_hi; ppo.A1lo = h_lo; ppo.lda1 = DETn; ppo.K1 = DETn;
        ppo.A2hi = obs_hi + (long)t * Ee; ppo.A2lo = obs_lo + (long)t * Ee; ppo.lda2 = (long)Tt * Ee;
        ppo.Bhi = Bpo_hi; ppo.Blo = Bpo_lo; ppo.ldb = 3072;
        ppo.bias = b_post_in; ppo.K = 3072; ppo.Ntiles = HIDn / 64;
        ppo.epi = 1; ppo.Chi = pf_hi; ppo.Clo = pf_lo; ppo.ldch = HIDn;
        TG ppr = {};
        ppr.A1hi = h_hi; ppr.A1lo = h_lo; ppr.lda1 = DETn; ppr.K1 = DETn;
        ppr.Bhi = Bpr_hi; ppr.Blo = Bpr_lo; ppr.ldb = DETn;
        ppr.bias = b_prior_in; ppr.K = DETn; ppr.Ntiles = HIDn / 64;
        ppr.epi = 1; ppr.Chi = rf_hi; ppr.Clo = rf_lo; ppr.ldch = HIDn;
        tgemm_kernel<64, 64, 2, 4><<<dim3(4, HIDn / 64, 2), 256, SMEM_SMALL>>>(ppo, ppr);

        // L5 (fused with finalize): interleaved ms heads; posterior also rsamples z
        TG qpm = {};
        qpm.A1hi = pf_hi; qpm.A1lo = pf_lo; qpm.lda1 = HIDn; qpm.K1 = HIDn;
        qpm.Bhi = Bpm_hi; qpm.Blo = Bpm_lo; qpm.ldb = HIDn;
        qpm.bias = bpm_i; qpm.K = HIDn; qpm.Ntiles = 512 / 64;
        qpm.epi = 2; qpm.ldo = (long)Tt * STOn;
        qpm.o_m = out_pm + (long)t * STOn; qpm.o_s = out_ps + (long)t * STOn;
        qpm.o_z = out_z + (long)t * STOn; qpm.eps = noise + (long)t * STOn;
        qpm.zhi = z_hi; qpm.zlo = z_lo;
        TG qqm = {};
        qqm.A1hi = rf_hi; qqm.A1lo = rf_lo; qqm.lda1 = HIDn; qqm.K1 = HIDn;
        qqm.Bhi = Bqm_hi; qqm.Blo = Bqm_lo; qqm.ldb = HIDn;
        qqm.bias = bqm_i; qqm.K = HIDn; qqm.Ntiles = 512 / 64;
        qqm.epi = 2; qqm.ldo = (long)Tt * STOn;
        qqm.o_m = out_qm + (long)t * STOn; qqm.o_s = out_qs + (long)t * STOn;
        qqm.o_z = nullptr; qqm.eps = nullptr; qqm.zhi = nullptr; qqm.zlo = nullptr;
        tgemm_kernel<64, 64, 2, 4><<<dim3(4, 512 / 64, 2), 256, SMEM_SMALL>>>(qpm, qqm);
    }
}

// round 8
// speedup vs baseline: 4.8414x; 1.0687x over previous
#include <cuda_runtime.h>
#include <cuda_bf16.h>
#include <math.h>
#include <stdint.h>

// ---------------- problem constants ----------------
constexpr int Bb  = 256;
constexpr int Tt  = 64;
constexpr int Aa  = 64;
constexpr int Ee  = 1024;
constexpr int HIDn = 1024;
constexpr int DETn = 2048;
constexpr int STOn = 256;
constexpr int G3  = 3 * DETn;   // 6144

typedef __nv_bfloat16 bf16;

// ---------------- device-global scratch (no allocation allowed) ----------------
__device__ __align__(256) bf16 g_Bhh_hi [G3 * DETn],  g_Bhh_lo [G3 * DETn];
__device__ __align__(256) bf16 g_Bih_hi [G3 * HIDn],  g_Bih_lo [G3 * HIDn];
__device__ __align__(256) bf16 g_Brnn_hi[HIDn * 320], g_Brnn_lo[HIDn * 320];
__device__ __align__(256) bf16 g_Bpo_hi [HIDn * 3072],g_Bpo_lo [HIDn * 3072];
__device__ __align__(256) bf16 g_Bpr_hi [HIDn * DETn],g_Bpr_lo [HIDn * DETn];
__device__ __align__(256) bf16 g_Bpm_hi [512 * HIDn], g_Bpm_lo [512 * HIDn];   // interleaved rows
__device__ __align__(256) bf16 g_Bqm_hi [512 * HIDn], g_Bqm_lo [512 * HIDn];   // interleaved rows
__device__ __align__(256) float g_bpm_int[512], g_bqm_int[512];
__device__ __align__(256) bf16 g_obs_hi[Bb * Tt * Ee], g_obs_lo[Bb * Tt * Ee];
__device__ __align__(256) bf16 g_act_hi[Bb * Tt * Aa], g_act_lo[Bb * Tt * Aa];
__device__ __align__(256) bf16 g_zact  [Bb * Aa];      // stays zero
__device__ __align__(256) float g_h   [Bb * DETn];
__device__ __align__(256) bf16  g_h_hi[Bb * DETn], g_h_lo[Bb * DETn];
__device__ __align__(256) bf16  g_z_hi[Bb * STOn], g_z_lo[Bb * STOn];
__device__ __align__(256) bf16  g_rn_hi[Bb * HIDn], g_rn_lo[Bb * HIDn];
__device__ __align__(256) bf16  g_pf_hi[Bb * HIDn], g_pf_lo[Bb * HIDn];
__device__ __align__(256) bf16  g_rf_hi[Bb * HIDn], g_rf_lo[Bb * HIDn];
__device__ __align__(256) float g_gi[Bb * G3], g_gh[Bb * G3];

// ---------------- helpers ----------------
__device__ __forceinline__ uint32_t smem_u32(const void* p) {
    uint32_t a;
    asm("{ .reg .u64 t; cvta.to.shared.u64 t, %1; cvt.u32.u64 %0, t; }" : "=r"(a) : "l"(p));
    return a;
}
__device__ __forceinline__ void cpa16(uint32_t dst, const void* src) {
    asm volatile("cp.async.cg.shared.global [%0], [%1], 16;" :: "r"(dst), "l"(src) : "memory");
}
__device__ __forceinline__ void ldsm4(uint32_t& r0, uint32_t& r1, uint32_t& r2, uint32_t& r3,
                                      uint32_t a) {
    asm volatile("ldmatrix.sync.aligned.m8n8.x4.shared.b16 {%0,%1,%2,%3}, [%4];"
                 : "=r"(r0), "=r"(r1), "=r"(r2), "=r"(r3) : "r"(a));
}
__device__ __forceinline__ void mmabf(float* c, const uint32_t* a, const uint32_t* b) {
    asm volatile(
        "mma.sync.aligned.m16n8k16.row.col.f32.bf16.bf16.f32 "
        "{%0,%1,%2,%3}, {%4,%5,%6,%7}, {%8,%9}, {%0,%1,%2,%3};"
        : "+f"(c[0]), "+f"(c[1]), "+f"(c[2]), "+f"(c[3])
        : "r"(a[0]), "r"(a[1]), "r"(a[2]), "r"(a[3]), "r"(b[0]), "r"(b[1]));
}
__device__ __forceinline__ void split2(float v, bf16& h, bf16& l) {
    h = __float2bfloat16(v);
    l = __float2bfloat16(v - __bfloat162float(h));
}
__device__ __forceinline__ float softplusf(float x) {
    return (x > 20.f) ? x : log1pf(expf(x));
}

// ---------------- tensor GEMM: C[256,N] = epi([A1|A2] @ B^T + bias), 3-term bf16 split ----
struct TG {
    const bf16 *A1hi, *A1lo, *A2hi, *A2lo;
    const bf16 *Bhi, *Blo;
    const float* bias;
    float* C;            // epi 0
    bf16 *Chi, *Clo;     // epi 1
    float *o_m, *o_s, *o_z;   // epi 2
    const float* eps;         // epi 2 (posterior)
    bf16 *zhi, *zlo;          // epi 2 (posterior)
    long lda1, lda2, ldb, ldo;
    int K1, K, Ntiles, ldc, ldch, epi;
};

constexpr int ROW_B = 80;     // padded smem row (bytes) for 32 bf16
constexpr int NSTAGE = 3;

template<int NT, int BM, int BN, int WRM, int WRN>
__global__ __launch_bounds__(NT, (NT == 256 ? 2 : 1)) void tgemm_kernel(TG p0, TG p1) {
    constexpr int NA = (BM / WRM) / 16;
    constexpr int NB = (BN / WRN) / 16;
    constexpr int A_PART = BM * ROW_B;
    constexpr int B_PART = BN * ROW_B;
    constexpr int STAGE  = 2 * (A_PART + B_PART);

    TG p = blockIdx.z ? p1 : p0;
    if ((int)blockIdx.y >= p.Ntiles) return;

    extern __shared__ char smem[];
    const uint32_t sb = smem_u32(smem);
    const int tid = threadIdx.x, wid = tid >> 5, lane = tid & 31;
    const int m0 = blockIdx.x * BM, n0 = blockIdx.y * BN;
    const int wm = (wid % WRM) * (BM / WRM), wn = (wid / WRM) * (BN / WRN);

    auto loadChunk = [&](int c) {
        uint32_t stg = sb + (c % NSTAGE) * STAGE;
        long koff = (long)c * 32;
        const bf16 *ah, *al; long lda;
        if (koff < p.K1) { ah = p.A1hi; al = p.A1lo; lda = p.lda1; }
        else             { ah = p.A2hi; al = p.A2lo; lda = p.lda2; koff -= p.K1; }
        const bf16* a_hi = ah + (long)m0 * lda + koff;
        const bf16* a_lo = al + (long)m0 * lda + koff;
        const bf16* b_hi = p.Bhi + (long)n0 * p.ldb + (long)c * 32;
        const bf16* b_lo = p.Blo + (long)n0 * p.ldb + (long)c * 32;
#pragma unroll
        for (int o = tid; o < (BM + BN) * 4; o += NT) {
            int row = o >> 2, seg = o & 3;
            if (row < BM) {
                cpa16(stg + row * ROW_B + seg * 16,          a_hi + (long)row * lda + seg * 8);
                cpa16(stg + A_PART + row * ROW_B + seg * 16, a_lo + (long)row * lda + seg * 8);
            } else {
                int br = row - BM;
                cpa16(stg + 2 * A_PART + br * ROW_B + seg * 16,
                      b_hi + (long)br * p.ldb + seg * 8);
                cpa16(stg + 2 * A_PART + B_PART + br * ROW_B + seg * 16,
                      b_lo + (long)br * p.ldb + seg * 8);
            }
        }
        asm volatile("cp.async.commit_group;" ::: "memory");
    };

    float acc[NA][2 * NB][4];
#pragma unroll
    for (int i = 0; i < NA; i++)
#pragma unroll
        for (int j = 0; j < 2 * NB; j++)
#pragma unroll
            for (int k = 0; k < 4; k++) acc[i][j][k] = 0.f;

    const int nch = p.K >> 5;
    loadChunk(0);
    loadChunk(1);
    for (int c = 0; c < nch; c++) {
        asm volatile("cp.async.wait_group 1;" ::: "memory");   // chunk c resident
        __syncthreads();                                       // all warps done with c-1
        if (c + 2 < nch) loadChunk(c + 2);                     // overwrites stage of c-1: safe

        const uint32_t stg = sb + (c % NSTAGE) * STAGE;
#pragma unroll
        for (int kk = 0; kk < 2; kk++) {
            uint32_t Ah[NA][4], Al[NA][4], Bh[NB][4], Bl[NB][4];
#pragma unroll
            for (int mi = 0; mi < NA; mi++) {
                int row = wm + 16 * mi + (lane & 15);
                uint32_t ad = stg + row * ROW_B + kk * 32 + ((lane >> 4) << 4);
                ldsm4(Ah[mi][0], Ah[mi][1], Ah[mi][2], Ah[mi][3], ad);
                ldsm4(Al[mi][0], Al[mi][1], Al[mi][2], Al[mi][3], ad + A_PART);
            }
#pragma unroll
            for (int pp = 0; pp < NB; pp++) {
                int row = wn + 16 * pp + ((lane >> 4) << 3) + (lane & 7);
                uint32_t bd = stg + 2 * A_PART + row * ROW_B + kk * 32 + (((lane >> 3) & 1) << 4);
                ldsm4(Bh[pp][0], Bh[pp][1], Bh[pp][2], Bh[pp][3], bd);
                ldsm4(Bl[pp][0], Bl[pp][1], Bl[pp][2], Bl[pp][3], bd + B_PART);
            }
#pragma unroll
            for (int mi = 0; mi < NA; mi++)
#pragma unroll
                for (int pp = 0; pp < NB; pp++)
#pragma unroll
                    for (int tt = 0; tt < 2; tt++) {
                        float* ca = acc[mi][2 * pp + tt];
                        mmabf(ca, Ah[mi], &Bh[pp][2 * tt]);
                        mmabf(ca, Ah[mi], &Bl[pp][2 * tt]);
                        mmabf(ca, Al[mi], &Bh[pp][2 * tt]);
                    }
        }
    }

    // ---- epilogue ----
    const int mg = m0 + wm, ng = n0 + wn;
#pragma unroll
    for (int mi = 0; mi < NA; mi++) {
        int r = mg + 16 * mi + (lane >> 2);
#pragma unroll
        for (int nj = 0; nj < 2 * NB; nj++) {
            int cg = ng + 8 * nj + 2 * (lane & 3);
            float b0 = p.bias[cg], b1 = p.bias[cg + 1];
            float v00 = acc[mi][nj][0] + b0, v01 = acc[mi][nj][1] + b1;
            float v10 = acc[mi][nj][2] + b0, v11 = acc[mi][nj][3] + b1;
            if (p.epi == 1) {
                v00 = fmaxf(v00, 0.f); v01 = fmaxf(v01, 0.f);
                v10 = fmaxf(v10, 0.f); v11 = fmaxf(v11, 0.f);
                __nv_bfloat162 h2, l2;
                split2(v00, h2.x, l2.x); split2(v01, h2.y, l2.y);
                *(__nv_bfloat162*)(p.Chi + (long)r * p.ldch + cg) = h2;
                *(__nv_bfloat162*)(p.Clo + (long)r * p.ldch + cg) = l2;
                split2(v10, h2.x, l2.x); split2(v11, h2.y, l2.y);
                *(__nv_bfloat162*)(p.Chi + (long)(r + 8) * p.ldch + cg) = h2;
                *(__nv_bfloat162*)(p.Clo + (long)(r + 8) * p.ldch + cg) = l2;
            } else if (p.epi == 0) {
                float2 f2;
                f2.x = v00; f2.y = v01;
                *(float2*)(p.C + (long)r * p.ldc + cg) = f2;
                f2.x = v10; f2.y = v11;
                *(float2*)(p.C + (long)(r + 8) * p.ldc + cg) = f2;
            } else {
                int j = cg >> 1;
#pragma unroll
                for (int hh = 0; hh < 2; hh++) {
                    int rr = r + 8 * hh;
                    float mean = hh ? v10 : v00;
                    float sraw = hh ? v11 : v01;
                    float s = softplusf(sraw) + 0.1f;
                    long o = (long)rr * p.ldo + j;
                    p.o_m[o] = mean;
                    p.o_s[o] = s;
                    if (p.o_z) {
                        float zv = fmaf(s, p.eps[o], mean);
                        p.o_z[o] = zv;
                        split2(zv, p.zhi[rr * STOn + j], p.zlo[rr * STOn + j]);
                    }
                }
            }
        }
    }
}

constexpr int SMEM_BIG   = NSTAGE * 2 * (128 * ROW_B + 128 * ROW_B);  // 122880 (1 CTA/SM)
constexpr int SMEM_SMALL = NSTAGE * 2 * (64 * ROW_B + 64 * ROW_B);    // 61440  (2 CTA/SM)

// ---------------- GRU gate combine ----------------
__global__ __launch_bounds__(256) void gru_kernel(float* __restrict__ hout) {
    int idx = blockIdx.x * blockDim.x + threadIdx.x;
    int b = idx >> 9;
    int d = (idx & 511) << 2;
    const float* gi = g_gi + (long)b * G3 + d;
    const float* gh = g_gh + (long)b * G3 + d;
    float4 ir  = *(const float4*)(gi);
    float4 iu  = *(const float4*)(gi + DETn);
    float4 in_ = *(const float4*)(gi + 2 * DETn);
    float4 hr  = *(const float4*)(gh);
    float4 hu  = *(const float4*)(gh + DETn);
    float4 hn  = *(const float4*)(gh + 2 * DETn);
    float4 hp  = *(const float4*)(g_h + (long)b * DETn + d);
    float4 hs;
#define GRUC(X) { \
    float r = 1.f / (1.f + expf(-(ir.X + hr.X))); \
    float u = 1.f / (1.f + expf(-(iu.X + hu.X))); \
    float n = tanhf(in_.X + r * hn.X);            \
    hs.X = (1.f - u) * n + u * hp.X; }
    GRUC(x) GRUC(y) GRUC(z) GRUC(w)
#undef GRUC
    *(float4*)(g_h + (long)b * DETn + d) = hs;
    *(float4*)(hout + (long)b * (Tt * DETn) + d) = hs;
    long o = (long)b * DETn + d;
#pragma unroll
    for (int j = 0; j < 4; j++) {
        float v = (&hs.x)[j];
        split2(v, g_h_hi[o + j], g_h_lo[o + j]);
    }
}

// ---------------- merged prep: zero + elementwise splits + bias interleave ----------------
struct SplitJob { const float* src; bf16* hi; bf16* lo; long n; };

__global__ __launch_bounds__(256) void prep_split_kernel(
    SplitJob j0, SplitJob j1, SplitJob j2, SplitJob j3,
    const float* bpm, const float* bqm) {
    long stride = (long)gridDim.x * blockDim.x;
    long gt = (long)blockIdx.x * blockDim.x + threadIdx.x;
    for (long i = gt; i < Bb * DETn; i += stride) {
        g_h[i] = 0.f;
        g_h_hi[i] = __float2bfloat16(0.f);
        g_h_lo[i] = __float2bfloat16(0.f);
    }
    for (long i = gt; i < Bb * STOn; i += stride) {
        g_z_hi[i] = __float2bfloat16(0.f);
        g_z_lo[i] = __float2bfloat16(0.f);
    }
    for (long i = gt; i < 512; i += stride) {
        int c = (int)(i >> 1) + ((int)i & 1) * 256;
        g_bpm_int[i] = bpm[c];
        g_bqm_int[i] = bqm[c];
    }
    SplitJob jobs[4] = {j0, j1, j2, j3};
#pragma unroll
    for (int jj = 0; jj < 4; jj++) {
        SplitJob j = jobs[jj];
        for (long i = gt; i < j.n; i += stride)
            split2(j.src[i], j.hi[i], j.lo[i]);
    }
}

// ---------------- merged prep: transposed splits (optionally column-interleaved) --------
struct TJob { const float* src; bf16* hi; bf16* lo; int R, C, tileEnd, ilv; };

__global__ __launch_bounds__(256) void prep_tsplit_kernel(
    TJob a, TJob b, TJob c, TJob d, TJob e) {
    __shared__ float t[32][33];
    int bid = blockIdx.x;
    TJob j; int tileBase;
    if      (bid < a.tileEnd) { j = a; tileBase = 0; }
    else if (bid < b.tileEnd) { j = b; tileBase = a.tileEnd; }
    else if (bid < c.tileEnd) { j = c; tileBase = b.tileEnd; }
    else if (bid < d.tileEnd) { j = d; tileBase = c.tileEnd; }
    else                      { j = e; tileBase = d.tileEnd; }
    int tile = bid - tileBase;
    int tiles_x = j.C / 32;
    int c0 = (tile % tiles_x) * 32;
    int r0 = (tile / tiles_x) * 32;
    int tx = threadIdx.x & 31, ty = threadIdx.x >> 5;
    for (int i = ty; i < 32; i += 8)
        t[i][tx] = j.src[(long)(r0 + i) * j.C + c0 + tx];
    __syncthreads();
    for (int i = ty; i < 32; i += 8) {
        float v = t[tx][i];
        int cidx = c0 + i;
        int drow = j.ilv ? ((cidx < 256) ? 2 * cidx : 2 * (cidx - 256) + 1) : cidx;
        long o = (long)drow * j.R + r0 + tx;
        split2(v, j.hi[o], j.lo[o]);
    }
}

// ---------------- host orchestration ----------------
static void* sym(const void* s) { void* p; cudaGetSymbolAddress(&p, s); return p; }

extern "C" void kernel_launch(void* const* d_in, const int* in_sizes, int n_in,
                              void* d_out, int out_size) {
    const float* obs        = (const float*)d_in[0];
    const float* actions    = (const float*)d_in[1];
    const float* noise      = (const float*)d_in[4];
    const float* W_rnn      = (const float*)d_in[5];
    const float* b_rnn      = (const float*)d_in[6];
    const float* Wih        = (const float*)d_in[7];
    const float* Whh        = (const float*)d_in[8];
    const float* bih        = (const float*)d_in[9];
    const float* bhh        = (const float*)d_in[10];
    const float* W_post_in  = (const float*)d_in[11];
    const float* b_post_in  = (const float*)d_in[12];
    const float* W_post_ms  = (const float*)d_in[13];
    const float* b_post_ms  = (const float*)d_in[14];
    const float* W_prior_in = (const float*)d_in[15];
    const float* b_prior_in = (const float*)d_in[16];
    const float* W_prior_ms = (const float*)d_in[17];
    const float* b_prior_ms = (const float*)d_in[18];
    float* out = (float*)d_out;

    cudaFuncSetAttribute(tgemm_kernel<512, 128, 128, 4, 4>,
                         cudaFuncAttributeMaxDynamicSharedMemorySize, SMEM_BIG);
    cudaFuncSetAttribute(tgemm_kernel<256, 64, 64, 2, 4>,
                         cudaFuncAttributeMaxDynamicSharedMemorySize, SMEM_SMALL);

    bf16 *Bhh_hi = (bf16*)sym(g_Bhh_hi), *Bhh_lo = (bf16*)sym(g_Bhh_lo);
    bf16 *Bih_hi = (bf16*)sym(g_Bih_hi), *Bih_lo = (bf16*)sym(g_Bih_lo);
    bf16 *Brnn_hi = (bf16*)sym(g_Brnn_hi), *Brnn_lo = (bf16*)sym(g_Brnn_lo);
    bf16 *Bpo_hi = (bf16*)sym(g_Bpo_hi), *Bpo_lo = (bf16*)sym(g_Bpo_lo);
    bf16 *Bpr_hi = (bf16*)sym(g_Bpr_hi), *Bpr_lo = (bf16*)sym(g_Bpr_lo);
    bf16 *Bpm_hi = (bf16*)sym(g_Bpm_hi), *Bpm_lo = (bf16*)sym(g_Bpm_lo);
    bf16 *Bqm_hi = (bf16*)sym(g_Bqm_hi), *Bqm_lo = (bf16*)sym(g_Bqm_lo);
    float *bpm_i = (float*)sym(g_bpm_int), *bqm_i = (float*)sym(g_bqm_int);
    bf16 *obs_hi = (bf16*)sym(g_obs_hi), *obs_lo = (bf16*)sym(g_obs_lo);
    bf16 *act_hi = (bf16*)sym(g_act_hi), *act_lo = (bf16*)sym(g_act_lo);
    bf16 *zact   = (bf16*)sym(g_zact);
    bf16 *h_hi = (bf16*)sym(g_h_hi), *h_lo = (bf16*)sym(g_h_lo);
    bf16 *z_hi = (bf16*)sym(g_z_hi), *z_lo = (bf16*)sym(g_z_lo);
    bf16 *rn_hi = (bf16*)sym(g_rn_hi), *rn_lo = (bf16*)sym(g_rn_lo);
    bf16 *pf_hi = (bf16*)sym(g_pf_hi), *pf_lo = (bf16*)sym(g_pf_lo);
    bf16 *rf_hi = (bf16*)sym(g_rf_hi), *rf_lo = (bf16*)sym(g_rf_lo);
    float *gi_p = (float*)sym(g_gi), *gh_p = (float*)sym(g_gh);

    float* out_h  = out;
    float* out_z  = out_h  + (long)Bb * Tt * DETn;
    float* out_pm = out_z  + (long)Bb * Tt * STOn;
    float* out_ps = out_pm + (long)Bb * Tt * STOn;
    float* out_qm = out_ps + (long)Bb * Tt * STOn;
    float* out_qs = out_qm + (long)Bb * Tt * STOn;

    // ---- prep (2 launches) ----
    {
        SplitJob s0 = {Whh,     Bhh_hi, Bhh_lo, (long)G3 * DETn};
        SplitJob s1 = {Wih,     Bih_hi, Bih_lo, (long)G3 * HIDn};
        SplitJob s2 = {obs,     obs_hi, obs_lo, (long)Bb * Tt * Ee};
        SplitJob s3 = {actions, act_hi, act_lo, (long)Bb * Tt * Aa};
        prep_split_kernel<<<2048, 256>>>(s0, s1, s2, s3, b_post_ms, b_prior_ms);

        int t0 = (320 / 32) * (HIDn / 32);
        int t1 = t0 + (3072 / 32) * (HIDn / 32);
        int t2 = t1 + (DETn / 32) * (HIDn / 32);
        int t3 = t2 + (HIDn / 32) * (512 / 32);
        int t4 = t3 + (HIDn / 32) * (512 / 32);
        TJob a = {W_rnn,      Brnn_hi, Brnn_lo, 320,  HIDn, t0, 0};
        TJob b = {W_post_in,  Bpo_hi,  Bpo_lo,  3072, HIDn, t1, 0};
        TJob c = {W_prior_in, Bpr_hi,  Bpr_lo,  DETn, HIDn, t2, 0};
        TJob d = {W_post_ms,  Bpm_hi,  Bpm_lo,  HIDn, 512,  t3, 1};
        TJob e = {W_prior_ms, Bqm_hi,  Bqm_lo,  HIDn, 512,  t4, 1};
        prep_tsplit_kernel<<<t4, 256>>>(a, b, c, d, e);
    }

    for (int t = 0; t < Tt; t++) {
        // L1: rnn_in = relu([z_prev | a_prev] @ W_rnn + b) -> rn hi/lo
        TG prnn = {};
        prnn.A1hi = z_hi; prnn.A1lo = z_lo; prnn.lda1 = STOn; prnn.K1 = STOn;
        if (t > 0) { prnn.A2hi = act_hi + (long)(t - 1) * Aa; prnn.A2lo = act_lo + (long)(t - 1) * Aa; prnn.lda2 = (long)Tt * Aa; }
        else       { prnn.A2hi = zact; prnn.A2lo = zact; prnn.lda2 = Aa; }
        prnn.Bhi = Brnn_hi; prnn.Blo = Brnn_lo; prnn.ldb = 320;
        prnn.bias = b_rnn; prnn.K = 320; prnn.Ntiles = HIDn / 64;
        prnn.epi = 1; prnn.Chi = rn_hi; prnn.Clo = rn_lo; prnn.ldch = HIDn;
        tgemm_kernel<256, 64, 64, 2, 4><<<dim3(4, HIDn / 64, 1), 256, SMEM_SMALL>>>(prnn, prnn);

        // L2: z0: gh = h @ Whh^T + bhh ; z1: gi = rnn @ Wih^T + bih   (BM=BN=128, 512 thr)
        TG pgh = {};
        pgh.A1hi = h_hi; pgh.A1lo = h_lo; pgh.lda1 = DETn; pgh.K1 = DETn;
        pgh.Bhi = Bhh_hi; pgh.Blo = Bhh_lo; pgh.ldb = DETn;
        pgh.bias = bhh; pgh.K = DETn; pgh.Ntiles = G3 / 128;
        pgh.epi = 0; pgh.C = gh_p; pgh.ldc = G3;
        TG pgi = {};
        pgi.A1hi = rn_hi; pgi.A1lo = rn_lo; pgi.lda1 = HIDn; pgi.K1 = HIDn;
        pgi.Bhi = Bih_hi; pgi.Blo = Bih_lo; pgi.ldb = HIDn;
        pgi.bias = bih; pgi.K = HIDn; pgi.Ntiles = G3 / 128;
        pgi.epi = 0; pgi.C = gi_p; pgi.ldc = G3;
        tgemm_kernel<512, 128, 128, 4, 4><<<dim3(2, G3 / 128, 2), 512, SMEM_BIG>>>(pgh, pgi);

        // L3: GRU elementwise -> h
        gru_kernel<<<(Bb * DETn / 4) / 256, 256>>>(out_h + (long)t * DETn);

        // L4: z0: pf = relu([h|obs] @ Wpost_in + b) ; z1: rf = relu(h @ Wprior_in + b)
        TG ppo = {};
        ppo.A1hi = h_hi; ppo.A1lo = h_lo; ppo.lda1 = DETn; ppo.K1 = DETn;
        ppo.A2hi = obs_hi + (long)t * Ee; ppo.A2lo = obs_lo + (long)t * Ee; ppo.lda2 = (long)Tt * Ee;
        ppo.Bhi = Bpo_hi; ppo.Blo = Bpo_lo; ppo.ldb = 3072;
        ppo.bias = b_post_in; ppo.K = 3072; ppo.Ntiles = HIDn / 64;
        ppo.epi = 1; ppo.Chi = pf_hi; ppo.Clo = pf_lo; ppo.ldch = HIDn;
        TG ppr = {};
        ppr.A1hi = h_hi; ppr.A1lo = h_lo; ppr.lda1 = DETn; ppr.K1 = DETn;
        ppr.Bhi = Bpr_hi; ppr.Blo = Bpr_lo; ppr.ldb = DETn;
        ppr.bias = b_prior_in; ppr.K = DETn; ppr.Ntiles = HIDn / 64;
        ppr.epi = 1; ppr.Chi = rf_hi; ppr.Clo = rf_lo; ppr.ldch = HIDn;
        tgemm_kernel<256, 64, 64, 2, 4><<<dim3(4, HIDn / 64, 2), 256, SMEM_SMALL>>>(ppo, ppr);

        // L5 (fused with finalize): interleaved ms heads; posterior also rsamples z
        TG qpm = {};
        qpm.A1hi = pf_hi; qpm.A1lo = pf_lo; qpm.lda1 = HIDn; qpm.K1 = HIDn;
        qpm.Bhi = Bpm_hi; qpm.Blo = Bpm_lo; qpm.ldb = HIDn;
        qpm.bias = bpm_i; qpm.K = HIDn; qpm.Ntiles = 512 / 64;
        qpm.epi = 2; qpm.ldo = (long)Tt * STOn;
        qpm.o_m = out_pm + (long)t * STOn; qpm.o_s = out_ps + (long)t * STOn;
        qpm.o_z = out_z + (long)t * STOn; qpm.eps = noise + (long)t * STOn;
        qpm.zhi = z_hi; qpm.zlo = z_lo;
        TG qqm = {};
        qqm.A1hi = rf_hi; qqm.A1lo = rf_lo; qqm.lda1 = HIDn; qqm.K1 = HIDn;
        qqm.Bhi = Bqm_hi; qqm.Blo = Bqm_lo; qqm.ldb = HIDn;
        qqm.bias = bqm_i; qqm.K = HIDn; qqm.Ntiles = 512 / 64;
        qqm.epi = 2; qqm.ldo = (long)Tt * STOn;
        qqm.o_m = out_qm + (long)t * STOn; qqm.o_s = out_qs + (long)t * STOn;
        qqm.o_z = nullptr; qqm.eps = nullptr; qqm.zhi = nullptr; qqm.zlo = nullptr;
        tgemm_kernel<256, 64, 64, 2, 4><<<dim3(4, 512 / 64, 2), 256, SMEM_SMALL>>>(qpm, qqm);
    }
}